// round 4
// baseline (speedup 1.0000x reference)
#include <cuda_runtime.h>
#include <cuda_bf16.h>
#include <math.h>
#include <float.h>
#include <cstdint>

// Problem constants
#define BB 2
#define SS 2048
#define HH 4096
#define NHEAD 32
#define NKVH 2
#define HDIM 128
#define ROT 64
#define QKV_N ((NHEAD + 2*NKVH) * HDIM)   // 4608
#define TOKENS (BB*SS)                     // 4096

// Scratch (device globals; allocation-free)
__device__ float g_qkv[(size_t)TOKENS * QKV_N];    // 75.5 MB
__device__ float g_attn[(size_t)TOKENS * HH];      // 67 MB
__device__ float g_wt[(size_t)QKV_N * HH];         // 75.5 MB (transposed weights)

__device__ __forceinline__ float tf32r(float x) {
    float o; asm("cvt.rna.tf32.f32 %0, %1;" : "=f"(o) : "f"(x)); return o;
}

// mma.sync m16n8k8 tf32: D = A*B + D (fp32 accum)
__device__ __forceinline__ void mma_tf32(float* c, const uint32_t* a, const uint32_t* b) {
    asm volatile("mma.sync.aligned.m16n8k8.row.col.f32.tf32.tf32.f32 "
        "{%0,%1,%2,%3}, {%4,%5,%6,%7}, {%8,%9}, {%0,%1,%2,%3};"
        : "+f"(c[0]), "+f"(c[1]), "+f"(c[2]), "+f"(c[3])
        : "r"(a[0]), "r"(a[1]), "r"(a[2]), "r"(a[3]), "r"(b[0]), "r"(b[1]));
}

// ---------------------------------------------------------------------------
// Weight transpose + tf32 rounding: W[K,N] row-major -> Wt[N,K] row-major
// ---------------------------------------------------------------------------
__global__ __launch_bounds__(256)
void transpose_tf32_kernel(const float* __restrict__ W, float* __restrict__ Wt, int K, int N)
{
    __shared__ float t[32][33];
    const int n0 = blockIdx.x * 32;
    const int k0 = blockIdx.y * 32;
    const int x = threadIdx.x, y = threadIdx.y;   // 32 x 8
    #pragma unroll
    for (int j = 0; j < 32; j += 8)
        t[y + j][x] = W[(size_t)(k0 + y + j) * N + n0 + x];
    __syncthreads();
    #pragma unroll
    for (int j = 0; j < 32; j += 8)
        Wt[(size_t)(n0 + y + j) * K + k0 + x] = tf32r(t[x][y + j]);
}

// ---------------------------------------------------------------------------
// Tensor-core tf32 GEMM via mma.sync: C[M,N] = A[M,K] @ Bt[N,K]^T (+bias)
// BM=BN=128, BK=32, 256 threads = 8 warps (2 x 4), warp tile 64x32.
// ---------------------------------------------------------------------------
template<bool HAS_BIAS>
__global__ __launch_bounds__(256, 2)
void mma_gemm_kernel(const float* __restrict__ A, const float* __restrict__ Bt,
                     const float* __restrict__ bias, float* __restrict__ C,
                     int M, int N, int K)
{
    __shared__ float As[128][33];   // [m][k]
    __shared__ float Bs[128][33];   // [n][k]

    const int tid  = threadIdx.x;
    const int wid  = tid >> 5;
    const int lane = tid & 31;
    const int lg   = lane >> 2;      // group id 0..7
    const int lt   = lane & 3;       // thread-in-group 0..3
    const int m_warp = (wid & 1) * 64;
    const int n_warp = (wid >> 1) * 32;
    const int rowBase = blockIdx.y * 128;
    const int colBase = blockIdx.x * 128;

    float acc[4][4][4];
    #pragma unroll
    for (int i = 0; i < 4; ++i)
        #pragma unroll
        for (int j = 0; j < 4; ++j)
            #pragma unroll
            for (int r = 0; r < 4; ++r) acc[i][j][r] = 0.f;

    for (int kt = 0; kt < K; kt += 32) {
        // Load A tile (128 x 32) and B tile (128 x 32), tf32-rounded.
        #pragma unroll
        for (int p = 0; p < 4; ++p) {
            int idx = p * 256 + tid;          // 0..1023 float4 slots
            int r = idx >> 3;                 // row 0..127
            int q = (idx & 7) * 4;            // col 0..28
            float4 va = *(const float4*)&A[(size_t)(rowBase + r) * K + kt + q];
            As[r][q + 0] = tf32r(va.x); As[r][q + 1] = tf32r(va.y);
            As[r][q + 2] = tf32r(va.z); As[r][q + 3] = tf32r(va.w);
            float4 vb = *(const float4*)&Bt[(size_t)(colBase + r) * K + kt + q];
            Bs[r][q + 0] = vb.x; Bs[r][q + 1] = vb.y;   // Wt pre-rounded
            Bs[r][q + 2] = vb.z; Bs[r][q + 3] = vb.w;
        }
        __syncthreads();

        #pragma unroll
        for (int ks = 0; ks < 4; ++ks) {
            const int k0 = ks * 8;
            uint32_t afr[4][4], bfr[4][2];
            #pragma unroll
            for (int i = 0; i < 4; ++i) {
                int row = m_warp + i * 16 + lg;
                afr[i][0] = __float_as_uint(As[row    ][k0 + lt    ]);
                afr[i][1] = __float_as_uint(As[row + 8][k0 + lt    ]);
                afr[i][2] = __float_as_uint(As[row    ][k0 + lt + 4]);
                afr[i][3] = __float_as_uint(As[row + 8][k0 + lt + 4]);
            }
            #pragma unroll
            for (int j = 0; j < 4; ++j) {
                int nrow = n_warp + j * 8 + lg;
                bfr[j][0] = __float_as_uint(Bs[nrow][k0 + lt    ]);
                bfr[j][1] = __float_as_uint(Bs[nrow][k0 + lt + 4]);
            }
            #pragma unroll
            for (int i = 0; i < 4; ++i)
                #pragma unroll
                for (int j = 0; j < 4; ++j)
                    mma_tf32(acc[i][j], afr[i], bfr[j]);
        }
        __syncthreads();
    }

    // Epilogue: c0:(row, col) c1:(row, col+1) c2:(row+8, col) c3:(row+8, col+1)
    #pragma unroll
    for (int i = 0; i < 4; ++i) {
        #pragma unroll
        for (int j = 0; j < 4; ++j) {
            int row = rowBase + m_warp + i * 16 + lg;
            int col = colBase + n_warp + j * 8 + lt * 2;
            float b0 = 0.f, b1 = 0.f;
            if (HAS_BIAS) { b0 = bias[col]; b1 = bias[col + 1]; }
            float2 v0 = { acc[i][j][0] + b0, acc[i][j][1] + b1 };
            float2 v1 = { acc[i][j][2] + b0, acc[i][j][3] + b1 };
            *(float2*)&C[(size_t)row * N + col]       = v0;
            *(float2*)&C[(size_t)(row + 8) * N + col] = v1;
        }
    }
}

// ---------------------------------------------------------------------------
// GLM RoPE, in-place on g_qkv
// ---------------------------------------------------------------------------
__global__ void rope_kernel(float* __restrict__ qkv, const int* __restrict__ positions)
{
    int idx = blockIdx.x * blockDim.x + threadIdx.x;
    const int total = TOKENS * (NHEAD + NKVH) * (ROT / 2);
    if (idx >= total) return;
    int i    = idx & 31;
    int head = (idx >> 5) % (NHEAD + NKVH);
    int tok  = idx / ((NHEAD + NKVH) * 32);

    float pos = (float)positions[tok];
    float inv = __powf(10000.0f, -(float)i * (1.0f / 32.0f));
    float ang = pos * inv;
    float c, s;
    sincosf(ang, &s, &c);
    int col = (head < NHEAD) ? head * HDIM : (NHEAD * HDIM + (head - NHEAD) * HDIM);
    float* p = qkv + (size_t)tok * QKV_N + col + 2 * i;
    float x1 = p[0], x2 = p[1];
    p[0] = x1 * c - x2 * s;
    p[1] = x1 * s + x2 * c;
}

// ---------------------------------------------------------------------------
// Flash attention, fp32 SIMT (unchanged)
// ---------------------------------------------------------------------------
__global__ __launch_bounds__(256)
void flash_kernel(const float* __restrict__ qkv, float* __restrict__ attn_out)
{
    const int qt = blockIdx.x;
    const int bh = blockIdx.y;
    const int b  = bh >> 5;
    const int h  = bh & 31;
    const int kvh = h >> 4;

    extern __shared__ float sm[];
    float* Qs = sm;
    float* Ks = Qs + 64 * 132;
    float* Vs = Ks + 64 * 132;
    float* Ps = Vs + 64 * 132;

    const int tid = threadIdx.x;
    const int ty = tid >> 4;
    const int tx = tid & 15;
    const float scale = 0.08838834764831845f;

    const float* qbase = qkv + (size_t)(b * SS + qt * 64) * QKV_N + h * HDIM;
    #pragma unroll
    for (int r = 0; r < 8; ++r) {
        int lin = r * 1024 + tid * 4;
        int row = lin >> 7, col = lin & 127;
        *(float4*)&Qs[row * 132 + col] = *(const float4*)(qbase + (size_t)row * QKV_N + col);
    }

    float m_i[4], l_i[4], acc[4][8];
    #pragma unroll
    for (int i = 0; i < 4; ++i) {
        m_i[i] = -3.0e38f; l_i[i] = 0.f;
        #pragma unroll
        for (int j = 0; j < 8; ++j) acc[i][j] = 0.f;
    }
    __syncthreads();

    for (int kt = 0; kt <= qt; ++kt) {
        const float* kbase = qkv + (size_t)(b * SS + kt * 64) * QKV_N + NHEAD * HDIM + kvh * HDIM;
        const float* vbase = kbase + NKVH * HDIM;
        #pragma unroll
        for (int r = 0; r < 8; ++r) {
            int lin = r * 1024 + tid * 4;
            int row = lin >> 7, col = lin & 127;
            *(float4*)&Ks[row * 132 + col] = *(const float4*)(kbase + (size_t)row * QKV_N + col);
            *(float4*)&Vs[row * 132 + col] = *(const float4*)(vbase + (size_t)row * QKV_N + col);
        }
        __syncthreads();

        float s[4][4];
        #pragma unroll
        for (int i = 0; i < 4; ++i)
            #pragma unroll
            for (int j = 0; j < 4; ++j) s[i][j] = 0.f;

        for (int d = 0; d < 128; d += 4) {
            float4 qv[4], kv[4];
            #pragma unroll
            for (int i = 0; i < 4; ++i) qv[i] = *(float4*)&Qs[(ty * 4 + i) * 132 + d];
            #pragma unroll
            for (int j = 0; j < 4; ++j) kv[j] = *(float4*)&Ks[(tx * 4 + j) * 132 + d];
            #pragma unroll
            for (int i = 0; i < 4; ++i)
                #pragma unroll
                for (int j = 0; j < 4; ++j) {
                    s[i][j] = fmaf(qv[i].x, kv[j].x, s[i][j]);
                    s[i][j] = fmaf(qv[i].y, kv[j].y, s[i][j]);
                    s[i][j] = fmaf(qv[i].z, kv[j].z, s[i][j]);
                    s[i][j] = fmaf(qv[i].w, kv[j].w, s[i][j]);
                }
        }
        #pragma unroll
        for (int i = 0; i < 4; ++i)
            #pragma unroll
            for (int j = 0; j < 4; ++j) {
                s[i][j] *= scale;
                if (kt == qt && (tx * 4 + j) > (ty * 4 + i)) s[i][j] = -3.0e38f;
            }

        float alpha[4];
        #pragma unroll
        for (int i = 0; i < 4; ++i) {
            float mx = s[i][0];
            mx = fmaxf(mx, s[i][1]); mx = fmaxf(mx, s[i][2]); mx = fmaxf(mx, s[i][3]);
            #pragma unroll
            for (int o = 1; o < 16; o <<= 1)
                mx = fmaxf(mx, __shfl_xor_sync(0xffffffffu, mx, o));
            float newm = fmaxf(m_i[i], mx);
            alpha[i] = __expf(m_i[i] - newm);
            m_i[i] = newm;
            float rs = 0.f;
            #pragma unroll
            for (int j = 0; j < 4; ++j) {
                float p = __expf(s[i][j] - newm);
                s[i][j] = p;
                rs += p;
            }
            #pragma unroll
            for (int o = 1; o < 16; o <<= 1)
                rs += __shfl_xor_sync(0xffffffffu, rs, o);
            l_i[i] = l_i[i] * alpha[i] + rs;
        }

        #pragma unroll
        for (int i = 0; i < 4; ++i) {
            #pragma unroll
            for (int j = 0; j < 4; ++j)
                Ps[(ty * 4 + i) * 68 + tx * 4 + j] = s[i][j];
            #pragma unroll
            for (int j = 0; j < 8; ++j) acc[i][j] *= alpha[i];
        }
        __syncthreads();

        for (int k = 0; k < 64; ++k) {
            float pk[4];
            #pragma unroll
            for (int i = 0; i < 4; ++i) pk[i] = Ps[(ty * 4 + i) * 68 + k];
            float4 v0 = *(float4*)&Vs[k * 132 + tx * 8];
            float4 v1 = *(float4*)&Vs[k * 132 + tx * 8 + 4];
            #pragma unroll
            for (int i = 0; i < 4; ++i) {
                acc[i][0] = fmaf(pk[i], v0.x, acc[i][0]);
                acc[i][1] = fmaf(pk[i], v0.y, acc[i][1]);
                acc[i][2] = fmaf(pk[i], v0.z, acc[i][2]);
                acc[i][3] = fmaf(pk[i], v0.w, acc[i][3]);
                acc[i][4] = fmaf(pk[i], v1.x, acc[i][4]);
                acc[i][5] = fmaf(pk[i], v1.y, acc[i][5]);
                acc[i][6] = fmaf(pk[i], v1.z, acc[i][6]);
                acc[i][7] = fmaf(pk[i], v1.w, acc[i][7]);
            }
        }
        __syncthreads();
    }

    float* obase = attn_out + (size_t)(b * SS + qt * 64) * HH + h * HDIM;
    #pragma unroll
    for (int i = 0; i < 4; ++i) {
        float inv_l = 1.0f / l_i[i];
        int row = ty * 4 + i;
        float4 o0, o1;
        o0.x = acc[i][0] * inv_l; o0.y = acc[i][1] * inv_l;
        o0.z = acc[i][2] * inv_l; o0.w = acc[i][3] * inv_l;
        o1.x = acc[i][4] * inv_l; o1.y = acc[i][5] * inv_l;
        o1.z = acc[i][6] * inv_l; o1.w = acc[i][7] * inv_l;
        *(float4*)(obase + (size_t)row * HH + tx * 8)     = o0;
        *(float4*)(obase + (size_t)row * HH + tx * 8 + 4) = o1;
    }
}

// ---------------------------------------------------------------------------
extern "C" void kernel_launch(void* const* d_in, const int* in_sizes, int n_in,
                              void* d_out, int out_size)
{
    const float* hs      = (const float*)d_in[0];
    const float* w_qkv   = (const float*)d_in[1];
    const float* b_qkv   = (const float*)d_in[2];
    const float* w_dense = (const float*)d_in[3];
    const int*   pos     = (const int*)d_in[4];
    float* out = (float*)d_out;

    float *qkv_ptr, *attn_ptr, *wt_ptr;
    cudaGetSymbolAddress((void**)&qkv_ptr, g_qkv);
    cudaGetSymbolAddress((void**)&attn_ptr, g_attn);
    cudaGetSymbolAddress((void**)&wt_ptr, g_wt);

    // 1) Transpose + tf32-round w_qkv: [4096,4608] -> [4608,4096]
    transpose_tf32_kernel<<<dim3(QKV_N / 32, HH / 32), dim3(32, 8)>>>(w_qkv, wt_ptr, HH, QKV_N);

    // 2) QKV projection + bias (tensor cores, tf32)
    mma_gemm_kernel<true><<<dim3(QKV_N / 128, TOKENS / 128), 256>>>(
        hs, wt_ptr, b_qkv, qkv_ptr, TOKENS, QKV_N, HH);

    // 3) RoPE in place
    {
        int total = TOKENS * (NHEAD + NKVH) * (ROT / 2);
        rope_kernel<<<(total + 255) / 256, 256>>>(qkv_ptr, pos);
    }

    // 4) Flash attention (fp32 SIMT)
    {
        size_t smem = (3 * 64 * 132 + 64 * 68) * sizeof(float);
        cudaFuncSetAttribute(flash_kernel, cudaFuncAttributeMaxDynamicSharedMemorySize, (int)smem);
        flash_kernel<<<dim3(SS / 64, BB * NHEAD), 256, smem>>>(qkv_ptr, attn_ptr);
    }

    // 5) Transpose + tf32-round w_dense: [4096,4096] -> [4096,4096]
    transpose_tf32_kernel<<<dim3(HH / 32, HH / 32), dim3(32, 8)>>>(w_dense, wt_ptr, HH, HH);

    // 6) Dense projection (tensor cores, tf32)
    mma_gemm_kernel<false><<<dim3(HH / 128, TOKENS / 128), 256>>>(
        attn_ptr, wt_ptr, nullptr, out, TOKENS, HH, HH);
}

// round 5
// speedup vs baseline: 2.0554x; 2.0554x over previous
#include <cuda_runtime.h>
#include <cuda_bf16.h>
#include <math.h>
#include <float.h>
#include <cstdint>

// Problem constants
#define BB 2
#define SS 2048
#define HH 4096
#define NHEAD 32
#define NKVH 2
#define HDIM 128
#define ROT 64
#define QKV_N ((NHEAD + 2*NKVH) * HDIM)   // 4608
#define TOKENS (BB*SS)                     // 4096

// Scratch (device globals; allocation-free)
__device__ float g_qkv[(size_t)TOKENS * QKV_N];    // 75.5 MB
__device__ float g_attn[(size_t)TOKENS * HH];      // 67 MB
__device__ float g_wt[(size_t)QKV_N * HH];         // 75.5 MB (transposed weights)

__device__ __forceinline__ float tf32r(float x) {
    float o; asm("cvt.rna.tf32.f32 %0, %1;" : "=f"(o) : "f"(x)); return o;
}

// mma.sync m16n8k8 tf32: D = A*B + D (fp32 accum)
__device__ __forceinline__ void mma_tf32(float* c, const uint32_t* a, const uint32_t* b) {
    asm volatile("mma.sync.aligned.m16n8k8.row.col.f32.tf32.tf32.f32 "
        "{%0,%1,%2,%3}, {%4,%5,%6,%7}, {%8,%9}, {%0,%1,%2,%3};"
        : "+f"(c[0]), "+f"(c[1]), "+f"(c[2]), "+f"(c[3])
        : "r"(a[0]), "r"(a[1]), "r"(a[2]), "r"(a[3]), "r"(b[0]), "r"(b[1]));
}

// ---------------------------------------------------------------------------
// Weight transpose + tf32 rounding: W[K,N] row-major -> Wt[N,K] row-major
// ---------------------------------------------------------------------------
__global__ __launch_bounds__(256)
void transpose_tf32_kernel(const float* __restrict__ W, float* __restrict__ Wt, int K, int N)
{
    __shared__ float t[32][33];
    const int n0 = blockIdx.x * 32;
    const int k0 = blockIdx.y * 32;
    const int x = threadIdx.x, y = threadIdx.y;   // 32 x 8
    #pragma unroll
    for (int j = 0; j < 32; j += 8)
        t[y + j][x] = W[(size_t)(k0 + y + j) * N + n0 + x];
    __syncthreads();
    #pragma unroll
    for (int j = 0; j < 32; j += 8)
        Wt[(size_t)(n0 + y + j) * K + k0 + x] = tf32r(t[x][y + j]);
}

// ---------------------------------------------------------------------------
// Tensor-core tf32 GEMM via mma.sync: C[M,N] = A[M,K] @ Bt[N,K]^T (+bias)
// BM=BN=128, BK=32, 256 threads = 8 warps (2 x 4), warp tile 64x32.
// SMEM holds operands in FRAGMENT ORDER:
//   A: 16x8 sub-tiles, addr = (i16*4 + ks)*132 + lane*4 + reg   (LDS.128/thread)
//   B:  8x8 sub-tiles, addr = (j8*4  + ks)*68  + lane*2 + reg   (LDS.64/thread)
// Pads (132/68 = +4 floats) de-alias ks blocks across banks.
// Double-buffered: LDG(t+1) | MMA(t) | STS(t+1) | sync.
// ---------------------------------------------------------------------------
#define ABUF 4224   // 32 tiles * 132 floats
#define BBUF 4352   // 64 tiles * 68 floats
#define GM_SMEM_BYTES ((2*ABUF + 2*BBUF) * 4)   // 68608

template<bool HAS_BIAS>
__global__ __launch_bounds__(256, 1)
void mma_gemm_kernel(const float* __restrict__ A, const float* __restrict__ Bt,
                     const float* __restrict__ bias, float* __restrict__ C,
                     int M, int N, int K)
{
    extern __shared__ float sm[];
    float* Asm = sm;                 // 2 buffers of ABUF
    float* Bsm = sm + 2 * ABUF;      // 2 buffers of BBUF

    const int tid  = threadIdx.x;
    const int wid  = tid >> 5;
    const int lane = tid & 31;
    const int lg   = lane >> 2;      // 0..7
    const int lt   = lane & 3;       // 0..3
    const int m_warp = (wid & 1) * 64;
    const int n_warp = (wid >> 1) * 32;
    const int rowBase = blockIdx.y * 128;
    const int colBase = blockIdx.x * 128;

    // Per-thread fill indices (same for every ktile)
    int fr[4], fq[4];
    #pragma unroll
    for (int p = 0; p < 4; ++p) {
        int idx = p * 256 + tid;
        fr[p] = idx >> 3;            // row/ncol 0..127
        fq[p] = (idx & 7) * 4;       // k offset 0..28
    }

    float acc[4][4][4];
    #pragma unroll
    for (int i = 0; i < 4; ++i)
        #pragma unroll
        for (int j = 0; j < 4; ++j)
            #pragma unroll
            for (int r = 0; r < 4; ++r) acc[i][j][r] = 0.f;

    float4 aS[4], bS[4];

    // ---- pipeline helpers ----
    auto ldg_tiles = [&](int kt) {
        #pragma unroll
        for (int p = 0; p < 4; ++p) {
            aS[p] = *(const float4*)&A [(size_t)(rowBase + fr[p]) * K + kt + fq[p]];
            bS[p] = *(const float4*)&Bt[(size_t)(colBase + fr[p]) * K + kt + fq[p]];
        }
    };
    auto sts_tiles = [&](int buf) {
        #pragma unroll
        for (int p = 0; p < 4; ++p) {
            int r = fr[p], q = fq[p];
            int ks = q >> 3;
            int regb = (q >> 2) & 1;
            // A: tile (r>>4, ks), lane (r&7)*4+d, reg ((r>>3)&1) + 2*regb
            float* ap = Asm + buf * ABUF + (((r >> 4) * 4 + ks) * 132)
                        + ((r & 7) * 16) + ((r >> 3) & 1) + 2 * regb;
            ap[0]  = tf32r(aS[p].x);
            ap[4]  = tf32r(aS[p].y);
            ap[8]  = tf32r(aS[p].z);
            ap[12] = tf32r(aS[p].w);
            // B: tile (r>>3, ks), lane (r&7)*4+d, reg regb  (Wt pre-rounded)
            float* bp = Bsm + buf * BBUF + (((r >> 3) * 4 + ks) * 68)
                        + ((r & 7) * 8) + regb;
            bp[0] = bS[p].x;
            bp[2] = bS[p].y;
            bp[4] = bS[p].z;
            bp[6] = bS[p].w;
        }
    };
    auto mma_tile = [&](int buf) {
        const float* Ab = Asm + buf * ABUF + ((wid & 1) * 16) * 132 + lane * 4;
        const float* Bb = Bsm + buf * BBUF + ((wid >> 1) * 16) * 68 + lane * 2;
        #pragma unroll
        for (int ks = 0; ks < 4; ++ks) {
            uint32_t afr[4][4], bfr[4][2];
            #pragma unroll
            for (int i = 0; i < 4; ++i)
                *(float4*)afr[i] = *(const float4*)(Ab + (i * 4 + ks) * 132);
            #pragma unroll
            for (int j = 0; j < 4; ++j)
                *(float2*)bfr[j] = *(const float2*)(Bb + (j * 4 + ks) * 68);
            #pragma unroll
            for (int i = 0; i < 4; ++i)
                #pragma unroll
                for (int j = 0; j < 4; ++j)
                    mma_tf32(acc[i][j], afr[i], bfr[j]);
        }
    };

    // ---- main pipeline ----
    const int NIT = K / 32;
    ldg_tiles(0);
    sts_tiles(0);
    __syncthreads();

    for (int t = 0; t < NIT; ++t) {
        if (t + 1 < NIT) ldg_tiles((t + 1) * 32);
        mma_tile(t & 1);
        if (t + 1 < NIT) sts_tiles((t + 1) & 1);
        __syncthreads();
    }

    // Epilogue
    #pragma unroll
    for (int i = 0; i < 4; ++i) {
        #pragma unroll
        for (int j = 0; j < 4; ++j) {
            int row = rowBase + m_warp + i * 16 + lg;
            int col = colBase + n_warp + j * 8 + lt * 2;
            float b0 = 0.f, b1 = 0.f;
            if (HAS_BIAS) { b0 = bias[col]; b1 = bias[col + 1]; }
            float2 v0 = { acc[i][j][0] + b0, acc[i][j][1] + b1 };
            float2 v1 = { acc[i][j][2] + b0, acc[i][j][3] + b1 };
            *(float2*)&C[(size_t)row * N + col]       = v0;
            *(float2*)&C[(size_t)(row + 8) * N + col] = v1;
        }
    }
}

// ---------------------------------------------------------------------------
// GLM RoPE, in-place on g_qkv
// ---------------------------------------------------------------------------
__global__ void rope_kernel(float* __restrict__ qkv, const int* __restrict__ positions)
{
    int idx = blockIdx.x * blockDim.x + threadIdx.x;
    const int total = TOKENS * (NHEAD + NKVH) * (ROT / 2);
    if (idx >= total) return;
    int i    = idx & 31;
    int head = (idx >> 5) % (NHEAD + NKVH);
    int tok  = idx / ((NHEAD + NKVH) * 32);

    float pos = (float)positions[tok];
    float inv = __powf(10000.0f, -(float)i * (1.0f / 32.0f));
    float ang = pos * inv;
    float c, s;
    sincosf(ang, &s, &c);
    int col = (head < NHEAD) ? head * HDIM : (NHEAD * HDIM + (head - NHEAD) * HDIM);
    float* p = qkv + (size_t)tok * QKV_N + col + 2 * i;
    float x1 = p[0], x2 = p[1];
    p[0] = x1 * c - x2 * s;
    p[1] = x1 * s + x2 * c;
}

// ---------------------------------------------------------------------------
// Flash attention, fp32 SIMT (unchanged)
// ---------------------------------------------------------------------------
__global__ __launch_bounds__(256)
void flash_kernel(const float* __restrict__ qkv, float* __restrict__ attn_out)
{
    const int qt = blockIdx.x;
    const int bh = blockIdx.y;
    const int b  = bh >> 5;
    const int h  = bh & 31;
    const int kvh = h >> 4;

    extern __shared__ float sm[];
    float* Qs = sm;
    float* Ks = Qs + 64 * 132;
    float* Vs = Ks + 64 * 132;
    float* Ps = Vs + 64 * 132;

    const int tid = threadIdx.x;
    const int ty = tid >> 4;
    const int tx = tid & 15;
    const float scale = 0.08838834764831845f;

    const float* qbase = qkv + (size_t)(b * SS + qt * 64) * QKV_N + h * HDIM;
    #pragma unroll
    for (int r = 0; r < 8; ++r) {
        int lin = r * 1024 + tid * 4;
        int row = lin >> 7, col = lin & 127;
        *(float4*)&Qs[row * 132 + col] = *(const float4*)(qbase + (size_t)row * QKV_N + col);
    }

    float m_i[4], l_i[4], acc[4][8];
    #pragma unroll
    for (int i = 0; i < 4; ++i) {
        m_i[i] = -3.0e38f; l_i[i] = 0.f;
        #pragma unroll
        for (int j = 0; j < 8; ++j) acc[i][j] = 0.f;
    }
    __syncthreads();

    for (int kt = 0; kt <= qt; ++kt) {
        const float* kbase = qkv + (size_t)(b * SS + kt * 64) * QKV_N + NHEAD * HDIM + kvh * HDIM;
        const float* vbase = kbase + NKVH * HDIM;
        #pragma unroll
        for (int r = 0; r < 8; ++r) {
            int lin = r * 1024 + tid * 4;
            int row = lin >> 7, col = lin & 127;
            *(float4*)&Ks[row * 132 + col] = *(const float4*)(kbase + (size_t)row * QKV_N + col);
            *(float4*)&Vs[row * 132 + col] = *(const float4*)(vbase + (size_t)row * QKV_N + col);
        }
        __syncthreads();

        float s[4][4];
        #pragma unroll
        for (int i = 0; i < 4; ++i)
            #pragma unroll
            for (int j = 0; j < 4; ++j) s[i][j] = 0.f;

        for (int d = 0; d < 128; d += 4) {
            float4 qv[4], kv[4];
            #pragma unroll
            for (int i = 0; i < 4; ++i) qv[i] = *(float4*)&Qs[(ty * 4 + i) * 132 + d];
            #pragma unroll
            for (int j = 0; j < 4; ++j) kv[j] = *(float4*)&Ks[(tx * 4 + j) * 132 + d];
            #pragma unroll
            for (int i = 0; i < 4; ++i)
                #pragma unroll
                for (int j = 0; j < 4; ++j) {
                    s[i][j] = fmaf(qv[i].x, kv[j].x, s[i][j]);
                    s[i][j] = fmaf(qv[i].y, kv[j].y, s[i][j]);
                    s[i][j] = fmaf(qv[i].z, kv[j].z, s[i][j]);
                    s[i][j] = fmaf(qv[i].w, kv[j].w, s[i][j]);
                }
        }
        #pragma unroll
        for (int i = 0; i < 4; ++i)
            #pragma unroll
            for (int j = 0; j < 4; ++j) {
                s[i][j] *= scale;
                if (kt == qt && (tx * 4 + j) > (ty * 4 + i)) s[i][j] = -3.0e38f;
            }

        float alpha[4];
        #pragma unroll
        for (int i = 0; i < 4; ++i) {
            float mx = s[i][0];
            mx = fmaxf(mx, s[i][1]); mx = fmaxf(mx, s[i][2]); mx = fmaxf(mx, s[i][3]);
            #pragma unroll
            for (int o = 1; o < 16; o <<= 1)
                mx = fmaxf(mx, __shfl_xor_sync(0xffffffffu, mx, o));
            float newm = fmaxf(m_i[i], mx);
            alpha[i] = __expf(m_i[i] - newm);
            m_i[i] = newm;
            float rs = 0.f;
            #pragma unroll
            for (int j = 0; j < 4; ++j) {
                float p = __expf(s[i][j] - newm);
                s[i][j] = p;
                rs += p;
            }
            #pragma unroll
            for (int o = 1; o < 16; o <<= 1)
                rs += __shfl_xor_sync(0xffffffffu, rs, o);
            l_i[i] = l_i[i] * alpha[i] + rs;
        }

        #pragma unroll
        for (int i = 0; i < 4; ++i) {
            #pragma unroll
            for (int j = 0; j < 4; ++j)
                Ps[(ty * 4 + i) * 68 + tx * 4 + j] = s[i][j];
            #pragma unroll
            for (int j = 0; j < 8; ++j) acc[i][j] *= alpha[i];
        }
        __syncthreads();

        for (int k = 0; k < 64; ++k) {
            float pk[4];
            #pragma unroll
            for (int i = 0; i < 4; ++i) pk[i] = Ps[(ty * 4 + i) * 68 + k];
            float4 v0 = *(float4*)&Vs[k * 132 + tx * 8];
            float4 v1 = *(float4*)&Vs[k * 132 + tx * 8 + 4];
            #pragma unroll
            for (int i = 0; i < 4; ++i) {
                acc[i][0] = fmaf(pk[i], v0.x, acc[i][0]);
                acc[i][1] = fmaf(pk[i], v0.y, acc[i][1]);
                acc[i][2] = fmaf(pk[i], v0.z, acc[i][2]);
                acc[i][3] = fmaf(pk[i], v0.w, acc[i][3]);
                acc[i][4] = fmaf(pk[i], v1.x, acc[i][4]);
                acc[i][5] = fmaf(pk[i], v1.y, acc[i][5]);
                acc[i][6] = fmaf(pk[i], v1.z, acc[i][6]);
                acc[i][7] = fmaf(pk[i], v1.w, acc[i][7]);
            }
        }
        __syncthreads();
    }

    float* obase = attn_out + (size_t)(b * SS + qt * 64) * HH + h * HDIM;
    #pragma unroll
    for (int i = 0; i < 4; ++i) {
        float inv_l = 1.0f / l_i[i];
        int row = ty * 4 + i;
        float4 o0, o1;
        o0.x = acc[i][0] * inv_l; o0.y = acc[i][1] * inv_l;
        o0.z = acc[i][2] * inv_l; o0.w = acc[i][3] * inv_l;
        o1.x = acc[i][4] * inv_l; o1.y = acc[i][5] * inv_l;
        o1.z = acc[i][6] * inv_l; o1.w = acc[i][7] * inv_l;
        *(float4*)(obase + (size_t)row * HH + tx * 8)     = o0;
        *(float4*)(obase + (size_t)row * HH + tx * 8 + 4) = o1;
    }
}

// ---------------------------------------------------------------------------
extern "C" void kernel_launch(void* const* d_in, const int* in_sizes, int n_in,
                              void* d_out, int out_size)
{
    const float* hs      = (const float*)d_in[0];
    const float* w_qkv   = (const float*)d_in[1];
    const float* b_qkv   = (const float*)d_in[2];
    const float* w_dense = (const float*)d_in[3];
    const int*   pos     = (const int*)d_in[4];
    float* out = (float*)d_out;

    float *qkv_ptr, *attn_ptr, *wt_ptr;
    cudaGetSymbolAddress((void**)&qkv_ptr, g_qkv);
    cudaGetSymbolAddress((void**)&attn_ptr, g_attn);
    cudaGetSymbolAddress((void**)&wt_ptr, g_wt);

    cudaFuncSetAttribute(mma_gemm_kernel<true>,
                         cudaFuncAttributeMaxDynamicSharedMemorySize, GM_SMEM_BYTES);
    cudaFuncSetAttribute(mma_gemm_kernel<false>,
                         cudaFuncAttributeMaxDynamicSharedMemorySize, GM_SMEM_BYTES);

    // 1) Transpose + tf32-round w_qkv: [4096,4608] -> [4608,4096]
    transpose_tf32_kernel<<<dim3(QKV_N / 32, HH / 32), dim3(32, 8)>>>(w_qkv, wt_ptr, HH, QKV_N);

    // 2) QKV projection + bias (tensor cores, tf32)
    mma_gemm_kernel<true><<<dim3(QKV_N / 128, TOKENS / 128), 256, GM_SMEM_BYTES>>>(
        hs, wt_ptr, b_qkv, qkv_ptr, TOKENS, QKV_N, HH);

    // 3) RoPE in place
    {
        int total = TOKENS * (NHEAD + NKVH) * (ROT / 2);
        rope_kernel<<<(total + 255) / 256, 256>>>(qkv_ptr, pos);
    }

    // 4) Flash attention (fp32 SIMT)
    {
        size_t smem = (3 * 64 * 132 + 64 * 68) * sizeof(float);
        cudaFuncSetAttribute(flash_kernel, cudaFuncAttributeMaxDynamicSharedMemorySize, (int)smem);
        flash_kernel<<<dim3(SS / 64, BB * NHEAD), 256, smem>>>(qkv_ptr, attn_ptr);
    }

    // 5) Transpose + tf32-round w_dense: [4096,4096] -> [4096,4096]
    transpose_tf32_kernel<<<dim3(HH / 32, HH / 32), dim3(32, 8)>>>(w_dense, wt_ptr, HH, HH);

    // 6) Dense projection (tensor cores, tf32)
    mma_gemm_kernel<false><<<dim3(HH / 128, TOKENS / 128), 256, GM_SMEM_BYTES>>>(
        attn_ptr, wt_ptr, nullptr, out, TOKENS, HH, HH);
}

// round 6
// speedup vs baseline: 3.0974x; 1.5069x over previous
#include <cuda_runtime.h>
#include <cuda_bf16.h>
#include <math.h>
#include <float.h>
#include <cstdint>

// Problem constants
#define BB 2
#define SS 2048
#define HH 4096
#define NHEAD 32
#define NKVH 2
#define HDIM 128
#define ROT 64
#define QKV_N ((NHEAD + 2*NKVH) * HDIM)   // 4608
#define TOKENS (BB*SS)                     // 4096

// Scratch (device globals; allocation-free)
__device__ float g_qkv[(size_t)TOKENS * QKV_N];    // 75.5 MB
__device__ float g_attn[(size_t)TOKENS * HH];      // 67 MB
__device__ float g_wt[(size_t)QKV_N * HH];         // 75.5 MB (transposed weights)

__device__ __forceinline__ float tf32r(float x) {
    float o; asm("cvt.rna.tf32.f32 %0, %1;" : "=f"(o) : "f"(x)); return o;
}

// mma.sync m16n8k8 tf32: D = A*B + D (fp32 accum)
__device__ __forceinline__ void mma_tf32(float* c, const uint32_t* a, const uint32_t* b) {
    asm volatile("mma.sync.aligned.m16n8k8.row.col.f32.tf32.tf32.f32 "
        "{%0,%1,%2,%3}, {%4,%5,%6,%7}, {%8,%9}, {%0,%1,%2,%3};"
        : "+f"(c[0]), "+f"(c[1]), "+f"(c[2]), "+f"(c[3])
        : "r"(a[0]), "r"(a[1]), "r"(a[2]), "r"(a[3]), "r"(b[0]), "r"(b[1]));
}

// ---------------------------------------------------------------------------
// Weight transpose + tf32 rounding: W[K,N] row-major -> Wt[N,K] row-major
// ---------------------------------------------------------------------------
__global__ __launch_bounds__(256)
void transpose_tf32_kernel(const float* __restrict__ W, float* __restrict__ Wt, int K, int N)
{
    __shared__ float t[32][33];
    const int n0 = blockIdx.x * 32;
    const int k0 = blockIdx.y * 32;
    const int x = threadIdx.x, y = threadIdx.y;   // 32 x 8
    #pragma unroll
    for (int j = 0; j < 32; j += 8)
        t[y + j][x] = W[(size_t)(k0 + y + j) * N + n0 + x];
    __syncthreads();
    #pragma unroll
    for (int j = 0; j < 32; j += 8)
        Wt[(size_t)(n0 + y + j) * K + k0 + x] = tf32r(t[x][y + j]);
}

// ---------------------------------------------------------------------------
// Tensor-core tf32 GEMM via mma.sync (unchanged from round 5 - WORKING)
// ---------------------------------------------------------------------------
#define ABUF 4224   // 32 tiles * 132 floats
#define BBUF 4352   // 64 tiles * 68 floats
#define GM_SMEM_BYTES ((2*ABUF + 2*BBUF) * 4)   // 68608

template<bool HAS_BIAS>
__global__ __launch_bounds__(256, 1)
void mma_gemm_kernel(const float* __restrict__ A, const float* __restrict__ Bt,
                     const float* __restrict__ bias, float* __restrict__ C,
                     int M, int N, int K)
{
    extern __shared__ float sm[];
    float* Asm = sm;
    float* Bsm = sm + 2 * ABUF;

    const int tid  = threadIdx.x;
    const int wid  = tid >> 5;
    const int lane = tid & 31;
    const int lg   = lane >> 2;
    const int lt   = lane & 3;
    const int m_warp = (wid & 1) * 64;
    const int n_warp = (wid >> 1) * 32;
    const int rowBase = blockIdx.y * 128;
    const int colBase = blockIdx.x * 128;

    int fr[4], fq[4];
    #pragma unroll
    for (int p = 0; p < 4; ++p) {
        int idx = p * 256 + tid;
        fr[p] = idx >> 3;
        fq[p] = (idx & 7) * 4;
    }

    float acc[4][4][4];
    #pragma unroll
    for (int i = 0; i < 4; ++i)
        #pragma unroll
        for (int j = 0; j < 4; ++j)
            #pragma unroll
            for (int r = 0; r < 4; ++r) acc[i][j][r] = 0.f;

    float4 aS[4], bS[4];

    auto ldg_tiles = [&](int kt) {
        #pragma unroll
        for (int p = 0; p < 4; ++p) {
            aS[p] = *(const float4*)&A [(size_t)(rowBase + fr[p]) * K + kt + fq[p]];
            bS[p] = *(const float4*)&Bt[(size_t)(colBase + fr[p]) * K + kt + fq[p]];
        }
    };
    auto sts_tiles = [&](int buf) {
        #pragma unroll
        for (int p = 0; p < 4; ++p) {
            int r = fr[p], q = fq[p];
            int ks = q >> 3;
            int regb = (q >> 2) & 1;
            float* ap = Asm + buf * ABUF + (((r >> 4) * 4 + ks) * 132)
                        + ((r & 7) * 16) + ((r >> 3) & 1) + 2 * regb;
            ap[0]  = tf32r(aS[p].x);
            ap[4]  = tf32r(aS[p].y);
            ap[8]  = tf32r(aS[p].z);
            ap[12] = tf32r(aS[p].w);
            float* bp = Bsm + buf * BBUF + (((r >> 3) * 4 + ks) * 68)
                        + ((r & 7) * 8) + regb;
            bp[0] = bS[p].x;
            bp[2] = bS[p].y;
            bp[4] = bS[p].z;
            bp[6] = bS[p].w;
        }
    };
    auto mma_tile = [&](int buf) {
        const float* Ab = Asm + buf * ABUF + ((wid & 1) * 16) * 132 + lane * 4;
        const float* Bb = Bsm + buf * BBUF + ((wid >> 1) * 16) * 68 + lane * 2;
        #pragma unroll
        for (int ks = 0; ks < 4; ++ks) {
            uint32_t afr[4][4], bfr[4][2];
            #pragma unroll
            for (int i = 0; i < 4; ++i)
                *(float4*)afr[i] = *(const float4*)(Ab + (i * 4 + ks) * 132);
            #pragma unroll
            for (int j = 0; j < 4; ++j)
                *(float2*)bfr[j] = *(const float2*)(Bb + (j * 4 + ks) * 68);
            #pragma unroll
            for (int i = 0; i < 4; ++i)
                #pragma unroll
                for (int j = 0; j < 4; ++j)
                    mma_tf32(acc[i][j], afr[i], bfr[j]);
        }
    };

    const int NIT = K / 32;
    ldg_tiles(0);
    sts_tiles(0);
    __syncthreads();

    for (int t = 0; t < NIT; ++t) {
        if (t + 1 < NIT) ldg_tiles((t + 1) * 32);
        mma_tile(t & 1);
        if (t + 1 < NIT) sts_tiles((t + 1) & 1);
        __syncthreads();
    }

    #pragma unroll
    for (int i = 0; i < 4; ++i) {
        #pragma unroll
        for (int j = 0; j < 4; ++j) {
            int row = rowBase + m_warp + i * 16 + lg;
            int col = colBase + n_warp + j * 8 + lt * 2;
            float b0 = 0.f, b1 = 0.f;
            if (HAS_BIAS) { b0 = bias[col]; b1 = bias[col + 1]; }
            float2 v0 = { acc[i][j][0] + b0, acc[i][j][1] + b1 };
            float2 v1 = { acc[i][j][2] + b0, acc[i][j][3] + b1 };
            *(float2*)&C[(size_t)row * N + col]       = v0;
            *(float2*)&C[(size_t)(row + 8) * N + col] = v1;
        }
    }
}

// ---------------------------------------------------------------------------
// GLM RoPE, in-place on g_qkv
// ---------------------------------------------------------------------------
__global__ void rope_kernel(float* __restrict__ qkv, const int* __restrict__ positions)
{
    int idx = blockIdx.x * blockDim.x + threadIdx.x;
    const int total = TOKENS * (NHEAD + NKVH) * (ROT / 2);
    if (idx >= total) return;
    int i    = idx & 31;
    int head = (idx >> 5) % (NHEAD + NKVH);
    int tok  = idx / ((NHEAD + NKVH) * 32);

    float pos = (float)positions[tok];
    float inv = __powf(10000.0f, -(float)i * (1.0f / 32.0f));
    float ang = pos * inv;
    float c, s;
    sincosf(ang, &s, &c);
    int col = (head < NHEAD) ? head * HDIM : (NHEAD * HDIM + (head - NHEAD) * HDIM);
    float* p = qkv + (size_t)tok * QKV_N + col + 2 * i;
    float x1 = p[0], x2 = p[1];
    p[0] = x1 * c - x2 * s;
    p[1] = x1 * s + x2 * c;
}

// ---------------------------------------------------------------------------
// Flash attention on tensor cores (tf32 mma.sync).
// Block: 64 q-rows x 1 head, 128 threads (4 warps, 16 q-rows each).
// KV tile = 64. SMEM fragment-order layouts:
//   KF: B-frags of K,  [j(0..7)][kp(0..7)] * 136 floats  (ks-pairs packed -> LDS.128)
//   VF: B-frags of V^T,[j(0..15)][kp(0..3)] * 136 floats
//   PS: per-warp A-frags of P, [warp][ks(0..7)] * 132 floats
// Q kept in registers as A-frags (staged once via SMEM, conflict-free).
// ---------------------------------------------------------------------------
#define KF_FLOATS 8704
#define VF_FLOATS 8704
#define PS_FLOATS 4224
#define FL_SMEM_BYTES ((KF_FLOATS + VF_FLOATS + PS_FLOATS) * 4)   // 86528

__global__ __launch_bounds__(128)
void flash_mma_kernel(const float* __restrict__ qkv, float* __restrict__ attn_out)
{
    extern __shared__ float sm[];
    float* KF = sm;
    float* VF = sm + KF_FLOATS;
    float* PS = sm + KF_FLOATS + VF_FLOATS;

    const int qt = blockIdx.x;               // 0..31
    const int bh = blockIdx.y;               // 0..63
    const int b  = bh >> 5;
    const int h  = bh & 31;
    const int kvh = h >> 4;
    const int tid = threadIdx.x;
    const int wid = tid >> 5;
    const int lane = tid & 31;
    const int lg = lane >> 2;
    const int lt = lane & 3;
    const float scale = 0.08838834764831845f;

    // ---- Stage Q tile (64 x 128) through KF (linear 64x132), then to regs ----
    const float* qg = qkv + (size_t)(b * SS + qt * 64) * QKV_N + h * HDIM;
    #pragma unroll
    for (int p = 0; p < 16; ++p) {
        int idx = p * 128 + tid;
        int r = idx >> 5, c = (idx & 31) * 4;
        float4 v = *(const float4*)(qg + (size_t)r * QKV_N + c);
        float* d = KF + r * 132 + c;
        d[0] = v.x; d[1] = v.y; d[2] = v.z; d[3] = v.w;
    }
    __syncthreads();

    uint32_t qa[16][4];
    {
        const float* q0 = KF + (wid * 16 + lg) * 132;
        const float* q1 = q0 + 8 * 132;
        #pragma unroll
        for (int ks = 0; ks < 16; ++ks) {
            qa[ks][0] = __float_as_uint(tf32r(q0[ks * 8 + lt]));
            qa[ks][1] = __float_as_uint(tf32r(q1[ks * 8 + lt]));
            qa[ks][2] = __float_as_uint(tf32r(q0[ks * 8 + lt + 4]));
            qa[ks][3] = __float_as_uint(tf32r(q1[ks * 8 + lt + 4]));
        }
    }

    float oacc[16][4];
    #pragma unroll
    for (int j = 0; j < 16; ++j)
        #pragma unroll
        for (int r = 0; r < 4; ++r) oacc[j][r] = 0.f;
    float m0 = -3.0e38f, m1 = -3.0e38f, l0 = 0.f, l1 = 0.f;

    float* PW = PS + wid * 1056;
    const int row0g = qt * 64 + wid * 16 + lg;
    const int row1g = row0g + 8;

    for (int kt = 0; kt <= qt; ++kt) {
        __syncthreads();   // protect KF/VF (and Q staging on iter 0) before refill

        // ---- cooperative fill of KF (K B-frags) and VF (V^T B-frags) ----
        const float* kg = qkv + (size_t)(b * SS + kt * 64) * QKV_N + NHEAD * HDIM + kvh * HDIM;
        const float* vg = kg + NKVH * HDIM;
        #pragma unroll
        for (int p = 0; p < 16; ++p) {
            int idx = p * 128 + tid;
            int n = idx >> 5;             // kv row 0..63
            int c = (idx & 31) * 4;       // feature 0..124
            float kv4[4], vv4[4];
            *(float4*)kv4 = *(const float4*)(kg + (size_t)n * QKV_N + c);
            *(float4*)vv4 = *(const float4*)(vg + (size_t)n * QKV_N + c);
            #pragma unroll
            for (int u = 0; u < 4; ++u) {
                int f = c + u;
                // K: n-dim = kv row (n), k-dim = feature (f)
                KF[(((n >> 3) * 8) + (f >> 4)) * 136
                   + ((n & 7) * 4 + (f & 3)) * 4 + ((f >> 3) & 1) * 2 + ((f & 7) >> 2)]
                    = tf32r(kv4[u]);
                // V^T: n-dim = feature (f), k-dim = kv row (n)
                VF[(((f >> 3) * 4) + (n >> 4)) * 136
                   + ((f & 7) * 4 + (n & 3)) * 4 + ((n >> 3) & 1) * 2 + ((n & 7) >> 2)]
                    = tf32r(vv4[u]);
            }
        }
        __syncthreads();

        // ---- S = Q K^T : warp computes 16x64 ----
        float sacc[8][4];
        #pragma unroll
        for (int j = 0; j < 8; ++j)
            #pragma unroll
            for (int r = 0; r < 4; ++r) sacc[j][r] = 0.f;

        #pragma unroll
        for (int kp = 0; kp < 8; ++kp) {
            #pragma unroll
            for (int j = 0; j < 8; ++j) {
                float4 kb = *(const float4*)&KF[(j * 8 + kp) * 136 + lane * 4];
                uint32_t be[2] = { __float_as_uint(kb.x), __float_as_uint(kb.y) };
                uint32_t bo[2] = { __float_as_uint(kb.z), __float_as_uint(kb.w) };
                mma_tf32(sacc[j], qa[2 * kp],     be);
                mma_tf32(sacc[j], qa[2 * kp + 1], bo);
            }
        }

        // ---- scale + causal mask ----
        #pragma unroll
        for (int j = 0; j < 8; ++j)
            #pragma unroll
            for (int r = 0; r < 4; ++r) sacc[j][r] *= scale;
        if (kt == qt) {
            #pragma unroll
            for (int j = 0; j < 8; ++j) {
                int col = kt * 64 + j * 8 + 2 * lt;
                if (col     > row0g) sacc[j][0] = -3.0e38f;
                if (col + 1 > row0g) sacc[j][1] = -3.0e38f;
                if (col     > row1g) sacc[j][2] = -3.0e38f;
                if (col + 1 > row1g) sacc[j][3] = -3.0e38f;
            }
        }

        // ---- online softmax (rows lg / lg+8; reduce over quad lanes) ----
        float mx0 = -3.0e38f, mx1 = -3.0e38f;
        #pragma unroll
        for (int j = 0; j < 8; ++j) {
            mx0 = fmaxf(mx0, fmaxf(sacc[j][0], sacc[j][1]));
            mx1 = fmaxf(mx1, fmaxf(sacc[j][2], sacc[j][3]));
        }
        mx0 = fmaxf(mx0, __shfl_xor_sync(0xffffffffu, mx0, 1));
        mx0 = fmaxf(mx0, __shfl_xor_sync(0xffffffffu, mx0, 2));
        mx1 = fmaxf(mx1, __shfl_xor_sync(0xffffffffu, mx1, 1));
        mx1 = fmaxf(mx1, __shfl_xor_sync(0xffffffffu, mx1, 2));
        float nm0 = fmaxf(m0, mx0), nm1 = fmaxf(m1, mx1);
        float a0 = __expf(m0 - nm0), a1 = __expf(m1 - nm1);
        m0 = nm0; m1 = nm1;
        float rs0 = 0.f, rs1 = 0.f;
        #pragma unroll
        for (int j = 0; j < 8; ++j) {
            sacc[j][0] = __expf(sacc[j][0] - nm0);
            sacc[j][1] = __expf(sacc[j][1] - nm0);
            sacc[j][2] = __expf(sacc[j][2] - nm1);
            sacc[j][3] = __expf(sacc[j][3] - nm1);
            rs0 += sacc[j][0] + sacc[j][1];
            rs1 += sacc[j][2] + sacc[j][3];
        }
        rs0 += __shfl_xor_sync(0xffffffffu, rs0, 1);
        rs0 += __shfl_xor_sync(0xffffffffu, rs0, 2);
        rs1 += __shfl_xor_sync(0xffffffffu, rs1, 1);
        rs1 += __shfl_xor_sync(0xffffffffu, rs1, 2);
        l0 = l0 * a0 + rs0;
        l1 = l1 * a1 + rs1;

        // rescale O
        #pragma unroll
        for (int j = 0; j < 16; ++j) {
            oacc[j][0] *= a0; oacc[j][1] *= a0;
            oacc[j][2] *= a1; oacc[j][3] *= a1;
        }

        // ---- store P as A-frags (per-warp private) ----
        {
            const int c0 = 2 * lt, c1 = 2 * lt + 1;
            const int o00 = (lg * 4 + (c0 & 3)) * 4 + ((c0 >> 2) & 1) * 2;
            const int o01 = (lg * 4 + (c1 & 3)) * 4 + ((c1 >> 2) & 1) * 2;
            #pragma unroll
            for (int j = 0; j < 8; ++j) {
                float* base = PW + j * 132;
                base[o00]     = tf32r(sacc[j][0]);
                base[o01]     = tf32r(sacc[j][1]);
                base[o00 + 1] = tf32r(sacc[j][2]);
                base[o01 + 1] = tf32r(sacc[j][3]);
            }
        }
        __syncwarp();

        // ---- O += P V ----
        #pragma unroll
        for (int kp = 0; kp < 4; ++kp) {
            uint32_t pa0[4], pa1[4];
            *(float4*)pa0 = *(const float4*)(PW + (2 * kp) * 132 + lane * 4);
            *(float4*)pa1 = *(const float4*)(PW + (2 * kp + 1) * 132 + lane * 4);
            #pragma unroll
            for (int j = 0; j < 16; ++j) {
                float4 vb = *(const float4*)&VF[(j * 4 + kp) * 136 + lane * 4];
                uint32_t be[2] = { __float_as_uint(vb.x), __float_as_uint(vb.y) };
                uint32_t bo[2] = { __float_as_uint(vb.z), __float_as_uint(vb.w) };
                mma_tf32(oacc[j], pa0, be);
                mma_tf32(oacc[j], pa1, bo);
            }
        }
        __syncwarp();
    }

    // ---- epilogue ----
    float il0 = 1.0f / l0, il1 = 1.0f / l1;
    float* ob = attn_out + (size_t)(b * SS + qt * 64 + wid * 16) * HH + h * HDIM;
    #pragma unroll
    for (int j = 0; j < 16; ++j) {
        int col = j * 8 + 2 * lt;
        float2 v0 = { oacc[j][0] * il0, oacc[j][1] * il0 };
        float2 v1 = { oacc[j][2] * il1, oacc[j][3] * il1 };
        *(float2*)&ob[(size_t)lg * HH + col]       = v0;
        *(float2*)&ob[(size_t)(lg + 8) * HH + col] = v1;
    }
}

// ---------------------------------------------------------------------------
extern "C" void kernel_launch(void* const* d_in, const int* in_sizes, int n_in,
                              void* d_out, int out_size)
{
    const float* hs      = (const float*)d_in[0];
    const float* w_qkv   = (const float*)d_in[1];
    const float* b_qkv   = (const float*)d_in[2];
    const float* w_dense = (const float*)d_in[3];
    const int*   pos     = (const int*)d_in[4];
    float* out = (float*)d_out;

    float *qkv_ptr, *attn_ptr, *wt_ptr;
    cudaGetSymbolAddress((void**)&qkv_ptr, g_qkv);
    cudaGetSymbolAddress((void**)&attn_ptr, g_attn);
    cudaGetSymbolAddress((void**)&wt_ptr, g_wt);

    cudaFuncSetAttribute(mma_gemm_kernel<true>,
                         cudaFuncAttributeMaxDynamicSharedMemorySize, GM_SMEM_BYTES);
    cudaFuncSetAttribute(mma_gemm_kernel<false>,
                         cudaFuncAttributeMaxDynamicSharedMemorySize, GM_SMEM_BYTES);
    cudaFuncSetAttribute(flash_mma_kernel,
                         cudaFuncAttributeMaxDynamicSharedMemorySize, FL_SMEM_BYTES);

    // 1) Transpose + tf32-round w_qkv: [4096,4608] -> [4608,4096]
    transpose_tf32_kernel<<<dim3(QKV_N / 32, HH / 32), dim3(32, 8)>>>(w_qkv, wt_ptr, HH, QKV_N);

    // 2) QKV projection + bias (tensor cores, tf32)
    mma_gemm_kernel<true><<<dim3(QKV_N / 128, TOKENS / 128), 256, GM_SMEM_BYTES>>>(
        hs, wt_ptr, b_qkv, qkv_ptr, TOKENS, QKV_N, HH);

    // 3) RoPE in place
    {
        int total = TOKENS * (NHEAD + NKVH) * (ROT / 2);
        rope_kernel<<<(total + 255) / 256, 256>>>(qkv_ptr, pos);
    }

    // 4) Flash attention (tensor cores, tf32)
    flash_mma_kernel<<<dim3(SS / 64, BB * NHEAD), 128, FL_SMEM_BYTES>>>(qkv_ptr, attn_ptr);

    // 5) Transpose + tf32-round w_dense: [4096,4096] -> [4096,4096]
    transpose_tf32_kernel<<<dim3(HH / 32, HH / 32), dim3(32, 8)>>>(w_dense, wt_ptr, HH, HH);

    // 6) Dense projection (tensor cores, tf32)
    mma_gemm_kernel<false><<<dim3(HH / 128, TOKENS / 128), 256, GM_SMEM_BYTES>>>(
        attn_ptr, wt_ptr, nullptr, out, TOKENS, HH, HH);
}

// round 7
// speedup vs baseline: 5.3191x; 1.7173x over previous
#include <cuda_runtime.h>
#include <cuda_fp16.h>
#include <math.h>
#include <float.h>
#include <cstdint>

// Problem constants
#define BB 2
#define SS 2048
#define HH 4096
#define NHEAD 32
#define NKVH 2
#define HDIM 128
#define ROT 64
#define QKV_N ((NHEAD + 2*NKVH) * HDIM)   // 4608
#define TOKENS (BB*SS)                     // 4096

// Scratch (device globals; allocation-free) — all fp16 now
__device__ __half g_qkv[(size_t)TOKENS * QKV_N];
__device__ __half g_attn[(size_t)TOKENS * HH];
__device__ __half g_wt[(size_t)QKV_N * HH];

// mma.sync m16n8k16 fp16 -> fp32 accum
__device__ __forceinline__ void mma_f16(float* c, const uint32_t* a, const uint32_t* b) {
    asm volatile("mma.sync.aligned.m16n8k16.row.col.f32.f16.f16.f32 "
        "{%0,%1,%2,%3}, {%4,%5,%6,%7}, {%8,%9}, {%0,%1,%2,%3};"
        : "+f"(c[0]), "+f"(c[1]), "+f"(c[2]), "+f"(c[3])
        : "r"(a[0]), "r"(a[1]), "r"(a[2]), "r"(a[3]), "r"(b[0]), "r"(b[1]));
}

__device__ __forceinline__ uint32_t pack_h2(float x, float y) {
    __half2 h = __floats2half2_rn(x, y);
    return *(uint32_t*)&h;
}

// ---------------------------------------------------------------------------
// Weight transpose + fp16 convert: W[K,N] fp32 row-major -> Wt[N,K] fp16
// ---------------------------------------------------------------------------
__global__ __launch_bounds__(256)
void transpose_f16_kernel(const float* __restrict__ W, __half* __restrict__ Wt, int K, int N)
{
    __shared__ float t[32][33];
    const int n0 = blockIdx.x * 32;
    const int k0 = blockIdx.y * 32;
    const int x = threadIdx.x, y = threadIdx.y;   // 32 x 8
    #pragma unroll
    for (int j = 0; j < 32; j += 8)
        t[y + j][x] = W[(size_t)(k0 + y + j) * N + n0 + x];
    __syncthreads();
    const int tid = y * 32 + x;
    #pragma unroll
    for (int p = 0; p < 2; ++p) {
        int task = p * 256 + tid;
        int r = task >> 4;        // n row 0..31
        int c = task & 15;        // k pair 0..15
        __half2 h = __floats2half2_rn(t[2 * c][r], t[2 * c + 1][r]);
        *(__half2*)&Wt[(size_t)(n0 + r) * K + k0 + 2 * c] = h;
    }
}

// ---------------------------------------------------------------------------
// fp16 tensor-core GEMM: C[M,N] = A[M,K] @ Bt[N,K]^T (+bias)
// BM=BN=128, BK=32, 256 thr, 8 warps (2x4), warp tile 64x32, m16n8k16.
// Fragment-order SMEM (uint32 = half2 words):
//   A tiles (16x16): 128 words + 4 pad; word = lane*4 + rowbit + 2*kbit
//   B tiles (8x16):   64 words + 4 pad; word = lane*2 + kbit
// QKV mode: A fp32 (cvt on store), C half + bias. Dense: A half, C float.
// ---------------------------------------------------------------------------
template<bool QKV>
__global__ __launch_bounds__(256, 1)
void mma_gemm_f16(const void* __restrict__ Av, const __half* __restrict__ Bt,
                  const float* __restrict__ bias, void* __restrict__ Cv,
                  int M, int N, int K)
{
    __shared__ uint32_t smw[8576];
    uint32_t* Asm = smw;             // 2 x 2112 words (16 tiles x 132)
    uint32_t* Bsm = smw + 4224;      // 2 x 2176 words (32 tiles x 68)

    const float*  Af = (const float*)Av;
    const __half* Ah = (const __half*)Av;

    const int tid  = threadIdx.x;
    const int wid  = tid >> 5;
    const int lane = tid & 31;
    const int lg   = lane >> 2;
    const int lt   = lane & 3;
    const int m_warp = (wid & 1) * 64;
    const int n_warp = (wid >> 1) * 32;
    const int rowBase = blockIdx.y * 128;
    const int colBase = blockIdx.x * 128;

    int fr[4], fq[4];
    #pragma unroll
    for (int p = 0; p < 4; ++p) {
        int idx = p * 256 + tid;
        fr[p] = idx >> 3;            // row/ncol 0..127
        fq[p] = (idx & 7) * 4;       // k offset 0..28
    }

    float acc[4][4][4];
    #pragma unroll
    for (int i = 0; i < 4; ++i)
        #pragma unroll
        for (int j = 0; j < 4; ++j)
            #pragma unroll
            for (int r = 0; r < 4; ++r) acc[i][j][r] = 0.f;

    float4 aSf[4]; uint2 aSh[4]; uint2 bS[4];

    auto ldg_tiles = [&](int kt) {
        #pragma unroll
        for (int p = 0; p < 4; ++p) {
            if (QKV) aSf[p] = *(const float4*)&Af[(size_t)(rowBase + fr[p]) * K + kt + fq[p]];
            else     aSh[p] = *(const uint2*)&Ah[(size_t)(rowBase + fr[p]) * K + kt + fq[p]];
            bS[p] = *(const uint2*)&Bt[(size_t)(colBase + fr[p]) * K + kt + fq[p]];
        }
    };
    auto sts_tiles = [&](int buf) {
        #pragma unroll
        for (int p = 0; p < 4; ++p) {
            int r = fr[p], q = fq[p];
            int lt0 = (q & 7) >> 1;            // 0 or 2
            int kbit = (q >> 3) & 1;
            uint32_t h0, h1;
            if (QKV) { h0 = pack_h2(aSf[p].x, aSf[p].y); h1 = pack_h2(aSf[p].z, aSf[p].w); }
            else     { h0 = aSh[p].x; h1 = aSh[p].y; }
            int wA = ((r >> 4) * 2 + (q >> 4)) * 132
                     + ((r & 7) * 4 + lt0) * 4 + ((r >> 3) & 1) + 2 * kbit;
            Asm[buf * 2112 + wA]     = h0;
            Asm[buf * 2112 + wA + 4] = h1;
            int wB = ((r >> 3) * 2 + (q >> 4)) * 68
                     + ((r & 7) * 4 + lt0) * 2 + kbit;
            Bsm[buf * 2176 + wB]     = bS[p].x;
            Bsm[buf * 2176 + wB + 2] = bS[p].y;
        }
    };
    auto mma_tile = [&](int buf) {
        const uint32_t* Ab = Asm + buf * 2112 + (wid & 1) * 1056 + lane * 4;
        const uint32_t* Bb = Bsm + buf * 2176 + (wid >> 1) * 544 + lane * 2;
        #pragma unroll
        for (int ks = 0; ks < 2; ++ks) {
            uint32_t afr[4][4], bfr[4][2];
            #pragma unroll
            for (int i = 0; i < 4; ++i)
                *(uint4*)afr[i] = *(const uint4*)(Ab + (i * 2 + ks) * 132);
            #pragma unroll
            for (int j = 0; j < 4; ++j)
                *(uint2*)bfr[j] = *(const uint2*)(Bb + (j * 2 + ks) * 68);
            #pragma unroll
            for (int i = 0; i < 4; ++i)
                #pragma unroll
                for (int j = 0; j < 4; ++j)
                    mma_f16(acc[i][j], afr[i], bfr[j]);
        }
    };

    const int NIT = K / 32;
    ldg_tiles(0);
    sts_tiles(0);
    __syncthreads();

    for (int t = 0; t < NIT; ++t) {
        if (t + 1 < NIT) ldg_tiles((t + 1) * 32);
        mma_tile(t & 1);
        if (t + 1 < NIT) sts_tiles((t + 1) & 1);
        __syncthreads();
    }

    #pragma unroll
    for (int i = 0; i < 4; ++i) {
        #pragma unroll
        for (int j = 0; j < 4; ++j) {
            int row = rowBase + m_warp + i * 16 + lg;
            int col = colBase + n_warp + j * 8 + lt * 2;
            if (QKV) {
                __half* C = (__half*)Cv;
                float b0 = bias[col], b1 = bias[col + 1];
                *(__half2*)&C[(size_t)row * N + col] =
                    __floats2half2_rn(acc[i][j][0] + b0, acc[i][j][1] + b1);
                *(__half2*)&C[(size_t)(row + 8) * N + col] =
                    __floats2half2_rn(acc[i][j][2] + b0, acc[i][j][3] + b1);
            } else {
                float* C = (float*)Cv;
                float2 v0 = { acc[i][j][0], acc[i][j][1] };
                float2 v1 = { acc[i][j][2], acc[i][j][3] };
                *(float2*)&C[(size_t)row * N + col]       = v0;
                *(float2*)&C[(size_t)(row + 8) * N + col] = v1;
            }
        }
    }
}

// ---------------------------------------------------------------------------
// GLM RoPE, in-place on fp16 qkv (rotation math in fp32)
// ---------------------------------------------------------------------------
__global__ void rope_kernel(__half* __restrict__ qkv, const int* __restrict__ positions)
{
    int idx = blockIdx.x * blockDim.x + threadIdx.x;
    const int total = TOKENS * (NHEAD + NKVH) * (ROT / 2);
    if (idx >= total) return;
    int i    = idx & 31;
    int head = (idx >> 5) % (NHEAD + NKVH);
    int tok  = idx / ((NHEAD + NKVH) * 32);

    float pos = (float)positions[tok];
    float inv = __powf(10000.0f, -(float)i * (1.0f / 32.0f));
    float ang = pos * inv;
    float c, s;
    sincosf(ang, &s, &c);
    int col = (head < NHEAD) ? head * HDIM : (NHEAD * HDIM + (head - NHEAD) * HDIM);
    __half2* p = (__half2*)(qkv + (size_t)tok * QKV_N + col + 2 * i);
    float2 x = __half22float2(*p);
    *p = __floats2half2_rn(x.x * c - x.y * s, x.x * s + x.y * c);
}

// ---------------------------------------------------------------------------
// Flash attention on fp16 tensor cores (m16n8k16).
// Block: 64 q-rows x 1 head, 128 threads (4 warps, 16 q-rows each). KV tile 64.
// SMEM (uint32 half2 words):
//   KF: B-frags of K   [n-tile 0..7][k16 chunk 0..7] x 68 words  (4352)
//   VF: B-frags of V^T [n-tile 0..15][kv chunk 0..3] x 68 words  (4352)
//   PS: per-warp A-frags of P, 4 tiles x 132 words               (2112)
// Q staged once through KF (64 x 68 words), kept in regs as A-frags.
// ---------------------------------------------------------------------------
__global__ __launch_bounds__(128, 3)
void flash_mma_kernel(const __half* __restrict__ qkv, __half* __restrict__ attn_out)
{
    __shared__ uint32_t sm[10816];
    uint32_t* KF = sm;
    uint32_t* VF = sm + 4352;
    uint32_t* PS = sm + 8704;

    const int qt = blockIdx.x;               // 0..31
    const int bh = blockIdx.y;               // 0..63
    const int b  = bh >> 5;
    const int h  = bh & 31;
    const int kvh = h >> 4;
    const int tid = threadIdx.x;
    const int wid = tid >> 5;
    const int lane = tid & 31;
    const int lg = lane >> 2;
    const int lt = lane & 3;
    const float scale = 0.08838834764831845f;  // 128^-0.5
    const int RW = QKV_N / 2;                  // row stride in words (2304)

    // ---- Stage Q tile (64 rows x 64 words) into KF, then extract A-frags ----
    const uint32_t* qg = (const uint32_t*)(qkv + (size_t)(b * SS + qt * 64) * QKV_N + h * HDIM);
    #pragma unroll
    for (int p = 0; p < 8; ++p) {
        int idx = p * 128 + tid;
        int row = idx >> 4;
        int wq = (idx & 15) * 4;
        uint4 v = *(const uint4*)(qg + (size_t)row * RW + wq);
        *(uint4*)&KF[row * 68 + wq] = v;
    }
    __syncthreads();

    uint32_t qa[8][4];
    {
        int base0 = (wid * 16 + lg) * 68 + lt;
        #pragma unroll
        for (int kc = 0; kc < 8; ++kc) {
            qa[kc][0] = KF[base0 + kc * 8];
            qa[kc][1] = KF[base0 + kc * 8 + 8 * 68];
            qa[kc][2] = KF[base0 + kc * 8 + 4];
            qa[kc][3] = KF[base0 + kc * 8 + 8 * 68 + 4];
        }
    }

    float oacc[16][4];
    #pragma unroll
    for (int j = 0; j < 16; ++j)
        #pragma unroll
        for (int r = 0; r < 4; ++r) oacc[j][r] = 0.f;
    float m0 = -3.0e38f, m1 = -3.0e38f, l0 = 0.f, l1 = 0.f;

    uint32_t* PW = PS + wid * 528;
    const int row0g = qt * 64 + wid * 16 + lg;
    const int row1g = row0g + 8;

    for (int kt = 0; kt <= qt; ++kt) {
        __syncthreads();   // protect KF/VF (and Q staging on iter 0)

        const uint32_t* kg = (const uint32_t*)(qkv
            + (size_t)(b * SS + kt * 64) * QKV_N + NHEAD * HDIM + kvh * HDIM);
        const uint32_t* vg = kg + NKVH * HDIM / 2;

        // ---- K fill: half2 pairs are already B-frag words ----
        #pragma unroll
        for (int p = 0; p < 16; ++p) {
            int idx = p * 128 + tid;
            int n = idx >> 5;             // kv row 0..63
            int wu = idx & 31;            // uint2 col
            uint2 u = *(const uint2*)(kg + (size_t)n * RW + wu * 2);
            int f = wu * 4;
            int base = ((n >> 3) * 8 + (f >> 4)) * 68
                       + ((n & 7) * 4 + ((f & 7) >> 1)) * 2 + ((f >> 3) & 1);
            KF[base]     = u.x;
            KF[base + 2] = u.y;
        }
        // ---- V fill: repack rows n,n+1 into (n,n+1) half2 k-pairs ----
        #pragma unroll
        for (int p = 0; p < 8; ++p) {
            int idx = p * 128 + tid;
            int np = idx >> 5;            // row pair 0..31
            int wu = idx & 31;
            int f = wu * 4;
            uint2 ua = *(const uint2*)(vg + (size_t)(2 * np) * RW + wu * 2);
            uint2 ub = *(const uint2*)(vg + (size_t)(2 * np + 1) * RW + wu * 2);
            __half2 a0 = *(__half2*)&ua.x, a1 = *(__half2*)&ua.y;
            __half2 b0 = *(__half2*)&ub.x, b1 = *(__half2*)&ub.y;
            __half2 w[4];
            w[0] = __halves2half2(__low2half(a0),  __low2half(b0));
            w[1] = __halves2half2(__high2half(a0), __high2half(b0));
            w[2] = __halves2half2(__low2half(a1),  __low2half(b1));
            w[3] = __halves2half2(__high2half(a1), __high2half(b1));
            int n = 2 * np;
            int klt = (n & 7) >> 1, kbit = (n >> 3) & 1, kch = n >> 4;
            #pragma unroll
            for (int u = 0; u < 4; ++u) {
                int ff = f + u;
                VF[((ff >> 3) * 4 + kch) * 68 + ((ff & 7) * 4 + klt) * 2 + kbit]
                    = *(uint32_t*)&w[u];
            }
        }
        __syncthreads();

        // ---- S = Q K^T : 16x64 per warp (8 n-tiles x 8 k16 chunks) ----
        float sacc[8][4];
        #pragma unroll
        for (int j = 0; j < 8; ++j)
            #pragma unroll
            for (int r = 0; r < 4; ++r) sacc[j][r] = 0.f;

        #pragma unroll
        for (int kp = 0; kp < 8; ++kp) {
            #pragma unroll
            for (int j = 0; j < 8; ++j) {
                uint32_t bfr[2];
                *(uint2*)bfr = *(const uint2*)&KF[(j * 8 + kp) * 68 + lane * 2];
                mma_f16(sacc[j], qa[kp], bfr);
            }
        }

        // ---- scale + causal mask ----
        #pragma unroll
        for (int j = 0; j < 8; ++j)
            #pragma unroll
            for (int r = 0; r < 4; ++r) sacc[j][r] *= scale;
        if (kt == qt) {
            #pragma unroll
            for (int j = 0; j < 8; ++j) {
                int col = kt * 64 + j * 8 + 2 * lt;
                if (col     > row0g) sacc[j][0] = -3.0e38f;
                if (col + 1 > row0g) sacc[j][1] = -3.0e38f;
                if (col     > row1g) sacc[j][2] = -3.0e38f;
                if (col + 1 > row1g) sacc[j][3] = -3.0e38f;
            }
        }

        // ---- online softmax (rows lg / lg+8; quad-lane reduce) ----
        float mx0 = -3.0e38f, mx1 = -3.0e38f;
        #pragma unroll
        for (int j = 0; j < 8; ++j) {
            mx0 = fmaxf(mx0, fmaxf(sacc[j][0], sacc[j][1]));
            mx1 = fmaxf(mx1, fmaxf(sacc[j][2], sacc[j][3]));
        }
        mx0 = fmaxf(mx0, __shfl_xor_sync(0xffffffffu, mx0, 1));
        mx0 = fmaxf(mx0, __shfl_xor_sync(0xffffffffu, mx0, 2));
        mx1 = fmaxf(mx1, __shfl_xor_sync(0xffffffffu, mx1, 1));
        mx1 = fmaxf(mx1, __shfl_xor_sync(0xffffffffu, mx1, 2));
        float nm0 = fmaxf(m0, mx0), nm1 = fmaxf(m1, mx1);
        float a0 = __expf(m0 - nm0), a1 = __expf(m1 - nm1);
        m0 = nm0; m1 = nm1;
        float rs0 = 0.f, rs1 = 0.f;
        #pragma unroll
        for (int j = 0; j < 8; ++j) {
            sacc[j][0] = __expf(sacc[j][0] - nm0);
            sacc[j][1] = __expf(sacc[j][1] - nm0);
            sacc[j][2] = __expf(sacc[j][2] - nm1);
            sacc[j][3] = __expf(sacc[j][3] - nm1);
            rs0 += sacc[j][0] + sacc[j][1];
            rs1 += sacc[j][2] + sacc[j][3];
        }
        rs0 += __shfl_xor_sync(0xffffffffu, rs0, 1);
        rs0 += __shfl_xor_sync(0xffffffffu, rs0, 2);
        rs1 += __shfl_xor_sync(0xffffffffu, rs1, 1);
        rs1 += __shfl_xor_sync(0xffffffffu, rs1, 2);
        l0 = l0 * a0 + rs0;
        l1 = l1 * a1 + rs1;

        #pragma unroll
        for (int j = 0; j < 16; ++j) {
            oacc[j][0] *= a0; oacc[j][1] *= a0;
            oacc[j][2] *= a1; oacc[j][3] *= a1;
        }

        // ---- store P as fp16 A-frags (per-warp private) ----
        #pragma unroll
        for (int j = 0; j < 8; ++j) {
            int w0 = (j >> 1) * 132 + lane * 4 + 2 * (j & 1);
            PW[w0]     = pack_h2(sacc[j][0], sacc[j][1]);   // row lg
            PW[w0 + 1] = pack_h2(sacc[j][2], sacc[j][3]);   // row lg+8
        }
        __syncwarp();

        // ---- O += P V  (16 n-tiles x 4 kv chunks) ----
        #pragma unroll
        for (int kp = 0; kp < 4; ++kp) {
            uint32_t pa[4];
            *(uint4*)pa = *(const uint4*)(PW + kp * 132 + lane * 4);
            #pragma unroll
            for (int j = 0; j < 16; ++j) {
                uint32_t vb[2];
                *(uint2*)vb = *(const uint2*)&VF[(j * 4 + kp) * 68 + lane * 2];
                mma_f16(oacc[j], pa, vb);
            }
        }
        __syncwarp();
    }

    // ---- epilogue: normalize, write fp16 attn ----
    float il0 = 1.0f / l0, il1 = 1.0f / l1;
    __half* ob = attn_out + (size_t)(b * SS + qt * 64 + wid * 16) * HH + h * HDIM;
    #pragma unroll
    for (int j = 0; j < 16; ++j) {
        int col = j * 8 + 2 * lt;
        *(__half2*)&ob[(size_t)lg * HH + col] =
            __floats2half2_rn(oacc[j][0] * il0, oacc[j][1] * il0);
        *(__half2*)&ob[(size_t)(lg + 8) * HH + col] =
            __floats2half2_rn(oacc[j][2] * il1, oacc[j][3] * il1);
    }
}

// ---------------------------------------------------------------------------
extern "C" void kernel_launch(void* const* d_in, const int* in_sizes, int n_in,
                              void* d_out, int out_size)
{
    const float* hs      = (const float*)d_in[0];
    const float* w_qkv   = (const float*)d_in[1];
    const float* b_qkv   = (const float*)d_in[2];
    const float* w_dense = (const float*)d_in[3];
    const int*   pos     = (const int*)d_in[4];
    float* out = (float*)d_out;

    __half *qkv_ptr, *attn_ptr, *wt_ptr;
    cudaGetSymbolAddress((void**)&qkv_ptr, g_qkv);
    cudaGetSymbolAddress((void**)&attn_ptr, g_attn);
    cudaGetSymbolAddress((void**)&wt_ptr, g_wt);

    // 1) Transpose + fp16 convert w_qkv: [4096,4608] -> [4608,4096] fp16
    transpose_f16_kernel<<<dim3(QKV_N / 32, HH / 32), dim3(32, 8)>>>(w_qkv, wt_ptr, HH, QKV_N);

    // 2) QKV projection + bias (fp16 tensor cores; A fp32 in, C fp16 out)
    mma_gemm_f16<true><<<dim3(QKV_N / 128, TOKENS / 128), 256>>>(
        hs, wt_ptr, b_qkv, qkv_ptr, TOKENS, QKV_N, HH);

    // 3) RoPE in place (fp16 storage, fp32 math)
    {
        int total = TOKENS * (NHEAD + NKVH) * (ROT / 2);
        rope_kernel<<<(total + 255) / 256, 256>>>(qkv_ptr, pos);
    }

    // 4) Flash attention (fp16 tensor cores)
    flash_mma_kernel<<<dim3(SS / 64, BB * NHEAD), 128>>>(qkv_ptr, attn_ptr);

    // 5) Transpose + fp16 convert w_dense: [4096,4096] -> [4096,4096] fp16
    transpose_f16_kernel<<<dim3(HH / 32, HH / 32), dim3(32, 8)>>>(w_dense, wt_ptr, HH, HH);

    // 6) Dense projection (fp16 tensor cores; A fp16, C fp32 out)
    mma_gemm_f16<false><<<dim3(HH / 128, TOKENS / 128), 256>>>(
        attn_ptr, wt_ptr, nullptr, out, TOKENS, HH, HH);
}

// round 8
// speedup vs baseline: 7.2717x; 1.3671x over previous
#include <cuda_runtime.h>
#include <cuda_fp16.h>
#include <math.h>
#include <float.h>
#include <cstdint>

// Problem constants
#define BB 2
#define SS 2048
#define HH 4096
#define NHEAD 32
#define NKVH 2
#define HDIM 128
#define ROT 64
#define QKV_N ((NHEAD + 2*NKVH) * HDIM)   // 4608
#define TOKENS (BB*SS)                     // 4096

// Scratch (device globals; allocation-free) — all fp16
__device__ __half g_qkv[(size_t)TOKENS * QKV_N];
__device__ __half g_attn[(size_t)TOKENS * HH];
__device__ __half g_wt[(size_t)QKV_N * HH];

// mma.sync m16n8k16 fp16 -> fp32 accum
__device__ __forceinline__ void mma_f16(float* c, const uint32_t* a, const uint32_t* b) {
    asm volatile("mma.sync.aligned.m16n8k16.row.col.f32.f16.f16.f32 "
        "{%0,%1,%2,%3}, {%4,%5,%6,%7}, {%8,%9}, {%0,%1,%2,%3};"
        : "+f"(c[0]), "+f"(c[1]), "+f"(c[2]), "+f"(c[3])
        : "r"(a[0]), "r"(a[1]), "r"(a[2]), "r"(a[3]), "r"(b[0]), "r"(b[1]));
}

__device__ __forceinline__ uint32_t pack_h2(float x, float y) {
    __half2 h = __floats2half2_rn(x, y);
    return *(uint32_t*)&h;
}

// ---------------------------------------------------------------------------
// Weight transpose + fp16 convert: W[K,N] fp32 row-major -> Wt[N,K] fp16
// ---------------------------------------------------------------------------
__global__ __launch_bounds__(256)
void transpose_f16_kernel(const float* __restrict__ W, __half* __restrict__ Wt, int K, int N)
{
    __shared__ float t[32][33];
    const int n0 = blockIdx.x * 32;
    const int k0 = blockIdx.y * 32;
    const int x = threadIdx.x, y = threadIdx.y;   // 32 x 8
    #pragma unroll
    for (int j = 0; j < 32; j += 8)
        t[y + j][x] = W[(size_t)(k0 + y + j) * N + n0 + x];
    __syncthreads();
    const int tid = y * 32 + x;
    #pragma unroll
    for (int p = 0; p < 2; ++p) {
        int task = p * 256 + tid;
        int r = task >> 4;        // n row 0..31
        int c = task & 15;        // k pair 0..15
        __half2 h = __floats2half2_rn(t[2 * c][r], t[2 * c + 1][r]);
        *(__half2*)&Wt[(size_t)(n0 + r) * K + k0 + 2 * c] = h;
    }
}

// ---------------------------------------------------------------------------
// fp16 tensor-core GEMM: C[M,N] = A[M,K] @ Bt[N,K]^T (+bias)
// BM=128, BN=256, BK=32, 256 thr, 8 warps (2x4), warp tile 64x64, m16n8k16.
// Fragment-order SMEM (uint32 = half2 words):
//   A tiles (16x16): 128 words + 4 pad (132); 16 tiles/buf = 2112 words
//   B tiles (8x16):   64 words + 4 pad (68);  64 tiles/buf = 4352 words
// QKV mode: A fp32 (cvt on store), C half + bias. Dense: A half, C float.
// ---------------------------------------------------------------------------
#define GM_SMEM_WORDS (2*2112 + 2*4352)           // 12928
#define GM_SMEM_BYTES (GM_SMEM_WORDS * 4)         // 51712

template<bool QKV>
__global__ __launch_bounds__(256, 1)
void mma_gemm_f16(const void* __restrict__ Av, const __half* __restrict__ Bt,
                  const float* __restrict__ bias, void* __restrict__ Cv,
                  int M, int N, int K)
{
    extern __shared__ uint32_t smw[];
    uint32_t* Asm = smw;             // 2 x 2112
    uint32_t* Bsm = smw + 4224;      // 2 x 4352

    const float*  Af = (const float*)Av;
    const __half* Ah = (const __half*)Av;

    const int tid  = threadIdx.x;
    const int wid  = tid >> 5;
    const int lane = tid & 31;
    const int lg   = lane >> 2;
    const int lt   = lane & 3;
    const int m_warp = (wid & 1) * 64;
    const int n_warp = (wid >> 1) * 64;
    const int rowBase = blockIdx.y * 128;
    const int colBase = blockIdx.x * 256;

    // A fill indices: 1024 float4/uint2 slots (128 rows x 8 k-slots)
    int fr[4], fq[4];
    #pragma unroll
    for (int p = 0; p < 4; ++p) {
        int idx = p * 256 + tid;
        fr[p] = idx >> 3;            // 0..127
        fq[p] = (idx & 7) * 4;       // 0..28
    }
    // B fill indices: 2048 uint2 slots (256 rows x 8 k-slots)
    int br[8], bq[8];
    #pragma unroll
    for (int p = 0; p < 8; ++p) {
        int idx = p * 256 + tid;
        br[p] = idx >> 3;            // 0..255
        bq[p] = (idx & 7) * 4;       // 0..28
    }

    float acc[4][8][4];
    #pragma unroll
    for (int i = 0; i < 4; ++i)
        #pragma unroll
        for (int j = 0; j < 8; ++j)
            #pragma unroll
            for (int r = 0; r < 4; ++r) acc[i][j][r] = 0.f;

    float4 aSf[4]; uint2 aSh[4]; uint2 bS[8];

    auto ldg_tiles = [&](int kt) {
        #pragma unroll
        for (int p = 0; p < 4; ++p) {
            if (QKV) aSf[p] = *(const float4*)&Af[(size_t)(rowBase + fr[p]) * K + kt + fq[p]];
            else     aSh[p] = *(const uint2*)&Ah[(size_t)(rowBase + fr[p]) * K + kt + fq[p]];
        }
        #pragma unroll
        for (int p = 0; p < 8; ++p)
            bS[p] = *(const uint2*)&Bt[(size_t)(colBase + br[p]) * K + kt + bq[p]];
    };
    auto sts_tiles = [&](int buf) {
        #pragma unroll
        for (int p = 0; p < 4; ++p) {
            int r = fr[p], q = fq[p];
            int lt0 = (q & 7) >> 1;
            int kbit = (q >> 3) & 1;
            uint32_t h0, h1;
            if (QKV) { h0 = pack_h2(aSf[p].x, aSf[p].y); h1 = pack_h2(aSf[p].z, aSf[p].w); }
            else     { h0 = aSh[p].x; h1 = aSh[p].y; }
            int wA = ((r >> 4) * 2 + (q >> 4)) * 132
                     + ((r & 7) * 4 + lt0) * 4 + ((r >> 3) & 1) + 2 * kbit;
            Asm[buf * 2112 + wA]     = h0;
            Asm[buf * 2112 + wA + 4] = h1;
        }
        #pragma unroll
        for (int p = 0; p < 8; ++p) {
            int n = br[p], q = bq[p];
            int lt0 = (q & 7) >> 1;
            int kbit = (q >> 3) & 1;
            int wB = ((n >> 3) * 2 + (q >> 4)) * 68
                     + ((n & 7) * 4 + lt0) * 2 + kbit;
            Bsm[buf * 4352 + wB]     = bS[p].x;
            Bsm[buf * 4352 + wB + 2] = bS[p].y;
        }
    };
    auto mma_tile = [&](int buf) {
        const uint32_t* Ab = Asm + buf * 2112 + (wid & 1) * 1056 + lane * 4;
        const uint32_t* Bb = Bsm + buf * 4352 + (wid >> 1) * 1088 + lane * 2;
        #pragma unroll
        for (int ks = 0; ks < 2; ++ks) {
            uint32_t afr[4][4], bfr[8][2];
            #pragma unroll
            for (int i = 0; i < 4; ++i)
                *(uint4*)afr[i] = *(const uint4*)(Ab + (i * 2 + ks) * 132);
            #pragma unroll
            for (int j = 0; j < 8; ++j)
                *(uint2*)bfr[j] = *(const uint2*)(Bb + (j * 2 + ks) * 68);
            #pragma unroll
            for (int i = 0; i < 4; ++i)
                #pragma unroll
                for (int j = 0; j < 8; ++j)
                    mma_f16(acc[i][j], afr[i], bfr[j]);
        }
    };

    const int NIT = K / 32;
    ldg_tiles(0);
    sts_tiles(0);
    __syncthreads();

    for (int t = 0; t < NIT; ++t) {
        if (t + 1 < NIT) ldg_tiles((t + 1) * 32);
        mma_tile(t & 1);
        if (t + 1 < NIT) sts_tiles((t + 1) & 1);
        __syncthreads();
    }

    #pragma unroll
    for (int i = 0; i < 4; ++i) {
        #pragma unroll
        for (int j = 0; j < 8; ++j) {
            int row = rowBase + m_warp + i * 16 + lg;
            int col = colBase + n_warp + j * 8 + lt * 2;
            if (QKV) {
                __half* C = (__half*)Cv;
                float b0 = bias[col], b1 = bias[col + 1];
                *(__half2*)&C[(size_t)row * N + col] =
                    __floats2half2_rn(acc[i][j][0] + b0, acc[i][j][1] + b1);
                *(__half2*)&C[(size_t)(row + 8) * N + col] =
                    __floats2half2_rn(acc[i][j][2] + b0, acc[i][j][3] + b1);
            } else {
                float* C = (float*)Cv;
                float2 v0 = { acc[i][j][0], acc[i][j][1] };
                float2 v1 = { acc[i][j][2], acc[i][j][3] };
                *(float2*)&C[(size_t)row * N + col]       = v0;
                *(float2*)&C[(size_t)(row + 8) * N + col] = v1;
            }
        }
    }
}

// ---------------------------------------------------------------------------
// GLM RoPE, in-place on fp16 qkv (rotation math in fp32)
// ---------------------------------------------------------------------------
__global__ void rope_kernel(__half* __restrict__ qkv, const int* __restrict__ positions)
{
    int idx = blockIdx.x * blockDim.x + threadIdx.x;
    const int total = TOKENS * (NHEAD + NKVH) * (ROT / 2);
    if (idx >= total) return;
    int i    = idx & 31;
    int head = (idx >> 5) % (NHEAD + NKVH);
    int tok  = idx / ((NHEAD + NKVH) * 32);

    float pos = (float)positions[tok];
    float inv = __powf(10000.0f, -(float)i * (1.0f / 32.0f));
    float ang = pos * inv;
    float c, s;
    sincosf(ang, &s, &c);
    int col = (head < NHEAD) ? head * HDIM : (NHEAD * HDIM + (head - NHEAD) * HDIM);
    __half2* p = (__half2*)(qkv + (size_t)tok * QKV_N + col + 2 * i);
    float2 x = __half22float2(*p);
    *p = __floats2half2_rn(x.x * c - x.y * s, x.x * s + x.y * c);
}

// ---------------------------------------------------------------------------
// Flash attention on fp16 tensor cores (m16n8k16).
// Block: 64 q-rows x 1 head, 128 threads (4 warps, 16 q-rows each). KV tile 64.
// SMEM (uint32 half2 words):
//   KF: B-frags of K   [n-tile 0..7][k16 chunk 0..7] x 68 words  (4352)
//   VF: B-frags of V^T [n-tile 0..15][kv chunk 0..3] x 68 words  (4352)
// P never touches SMEM: the S C-fragment layout IS the PV A-fragment layout.
// Q staged once through KF, kept in regs as A-frags.
// ---------------------------------------------------------------------------
__global__ __launch_bounds__(128, 3)
void flash_mma_kernel(const __half* __restrict__ qkv, __half* __restrict__ attn_out)
{
    __shared__ uint32_t sm[8704];
    uint32_t* KF = sm;
    uint32_t* VF = sm + 4352;

    const int qt = blockIdx.x;               // 0..31
    const int bh = blockIdx.y;               // 0..63
    const int b  = bh >> 5;
    const int h  = bh & 31;
    const int kvh = h >> 4;
    const int tid = threadIdx.x;
    const int wid = tid >> 5;
    const int lane = tid & 31;
    const int lg = lane >> 2;
    const int lt = lane & 3;
    const float scale = 0.08838834764831845f;  // 128^-0.5
    const int RW = QKV_N / 2;                  // row stride in words (2304)

    // ---- Stage Q tile (64 rows x 64 words) into KF, extract A-frags ----
    const uint32_t* qg = (const uint32_t*)(qkv + (size_t)(b * SS + qt * 64) * QKV_N + h * HDIM);
    #pragma unroll
    for (int p = 0; p < 8; ++p) {
        int idx = p * 128 + tid;
        int row = idx >> 4;
        int wq = (idx & 15) * 4;
        uint4 v = *(const uint4*)(qg + (size_t)row * RW + wq);
        *(uint4*)&KF[row * 68 + wq] = v;
    }
    __syncthreads();

    uint32_t qa[8][4];
    {
        int base0 = (wid * 16 + lg) * 68 + lt;
        #pragma unroll
        for (int kc = 0; kc < 8; ++kc) {
            qa[kc][0] = KF[base0 + kc * 8];
            qa[kc][1] = KF[base0 + kc * 8 + 8 * 68];
            qa[kc][2] = KF[base0 + kc * 8 + 4];
            qa[kc][3] = KF[base0 + kc * 8 + 8 * 68 + 4];
        }
    }

    float oacc[16][4];
    #pragma unroll
    for (int j = 0; j < 16; ++j)
        #pragma unroll
        for (int r = 0; r < 4; ++r) oacc[j][r] = 0.f;
    float m0 = -3.0e38f, m1 = -3.0e38f, l0 = 0.f, l1 = 0.f;

    const int row0g = qt * 64 + wid * 16 + lg;
    const int row1g = row0g + 8;

    for (int kt = 0; kt <= qt; ++kt) {
        __syncthreads();   // protect KF/VF (and Q staging on iter 0)

        const uint32_t* kg = (const uint32_t*)(qkv
            + (size_t)(b * SS + kt * 64) * QKV_N + NHEAD * HDIM + kvh * HDIM);
        const uint32_t* vg = kg + NKVH * HDIM / 2;

        // ---- K fill: half2 pairs are already B-frag words ----
        #pragma unroll
        for (int p = 0; p < 16; ++p) {
            int idx = p * 128 + tid;
            int n = idx >> 5;             // kv row 0..63
            int wu = idx & 31;            // uint2 col
            uint2 u = *(const uint2*)(kg + (size_t)n * RW + wu * 2);
            int f = wu * 4;
            int base = ((n >> 3) * 8 + (f >> 4)) * 68
                       + ((n & 7) * 4 + ((f & 7) >> 1)) * 2 + ((f >> 3) & 1);
            KF[base]     = u.x;
            KF[base + 2] = u.y;
        }
        // ---- V fill: repack rows n,n+1 into (n,n+1) half2 k-pairs ----
        #pragma unroll
        for (int p = 0; p < 8; ++p) {
            int idx = p * 128 + tid;
            int np = idx >> 5;            // row pair 0..31
            int wu = idx & 31;
            int f = wu * 4;
            uint2 ua = *(const uint2*)(vg + (size_t)(2 * np) * RW + wu * 2);
            uint2 ub = *(const uint2*)(vg + (size_t)(2 * np + 1) * RW + wu * 2);
            __half2 a0 = *(__half2*)&ua.x, a1 = *(__half2*)&ua.y;
            __half2 b0 = *(__half2*)&ub.x, b1 = *(__half2*)&ub.y;
            __half2 w[4];
            w[0] = __halves2half2(__low2half(a0),  __low2half(b0));
            w[1] = __halves2half2(__high2half(a0), __high2half(b0));
            w[2] = __halves2half2(__low2half(a1),  __low2half(b1));
            w[3] = __halves2half2(__high2half(a1), __high2half(b1));
            int n = 2 * np;
            int klt = (n & 7) >> 1, kbit = (n >> 3) & 1, kch = n >> 4;
            #pragma unroll
            for (int u = 0; u < 4; ++u) {
                int ff = f + u;
                VF[((ff >> 3) * 4 + kch) * 68 + ((ff & 7) * 4 + klt) * 2 + kbit]
                    = *(uint32_t*)&w[u];
            }
        }
        __syncthreads();

        // ---- S = Q K^T : 16x64 per warp ----
        float sacc[8][4];
        #pragma unroll
        for (int j = 0; j < 8; ++j)
            #pragma unroll
            for (int r = 0; r < 4; ++r) sacc[j][r] = 0.f;

        #pragma unroll
        for (int kp = 0; kp < 8; ++kp) {
            #pragma unroll
            for (int j = 0; j < 8; ++j) {
                uint32_t bfr[2];
                *(uint2*)bfr = *(const uint2*)&KF[(j * 8 + kp) * 68 + lane * 2];
                mma_f16(sacc[j], qa[kp], bfr);
            }
        }

        // ---- scale + causal mask ----
        #pragma unroll
        for (int j = 0; j < 8; ++j)
            #pragma unroll
            for (int r = 0; r < 4; ++r) sacc[j][r] *= scale;
        if (kt == qt) {
            #pragma unroll
            for (int j = 0; j < 8; ++j) {
                int col = kt * 64 + j * 8 + 2 * lt;
                if (col     > row0g) sacc[j][0] = -3.0e38f;
                if (col + 1 > row0g) sacc[j][1] = -3.0e38f;
                if (col     > row1g) sacc[j][2] = -3.0e38f;
                if (col + 1 > row1g) sacc[j][3] = -3.0e38f;
            }
        }

        // ---- online softmax (rows lg / lg+8; quad-lane reduce) ----
        float mx0 = -3.0e38f, mx1 = -3.0e38f;
        #pragma unroll
        for (int j = 0; j < 8; ++j) {
            mx0 = fmaxf(mx0, fmaxf(sacc[j][0], sacc[j][1]));
            mx1 = fmaxf(mx1, fmaxf(sacc[j][2], sacc[j][3]));
        }
        mx0 = fmaxf(mx0, __shfl_xor_sync(0xffffffffu, mx0, 1));
        mx0 = fmaxf(mx0, __shfl_xor_sync(0xffffffffu, mx0, 2));
        mx1 = fmaxf(mx1, __shfl_xor_sync(0xffffffffu, mx1, 1));
        mx1 = fmaxf(mx1, __shfl_xor_sync(0xffffffffu, mx1, 2));
        float nm0 = fmaxf(m0, mx0), nm1 = fmaxf(m1, mx1);
        float a0 = __expf(m0 - nm0), a1 = __expf(m1 - nm1);
        m0 = nm0; m1 = nm1;
        float rs0 = 0.f, rs1 = 0.f;
        #pragma unroll
        for (int j = 0; j < 8; ++j) {
            sacc[j][0] = __expf(sacc[j][0] - nm0);
            sacc[j][1] = __expf(sacc[j][1] - nm0);
            sacc[j][2] = __expf(sacc[j][2] - nm1);
            sacc[j][3] = __expf(sacc[j][3] - nm1);
            rs0 += sacc[j][0] + sacc[j][1];
            rs1 += sacc[j][2] + sacc[j][3];
        }
        rs0 += __shfl_xor_sync(0xffffffffu, rs0, 1);
        rs0 += __shfl_xor_sync(0xffffffffu, rs0, 2);
        rs1 += __shfl_xor_sync(0xffffffffu, rs1, 1);
        rs1 += __shfl_xor_sync(0xffffffffu, rs1, 2);
        l0 = l0 * a0 + rs0;
        l1 = l1 * a1 + rs1;

        #pragma unroll
        for (int j = 0; j < 16; ++j) {
            oacc[j][0] *= a0; oacc[j][1] *= a0;
            oacc[j][2] *= a1; oacc[j][3] *= a1;
        }

        // ---- O += P V : S C-frags ARE PV A-frags (pack in registers) ----
        #pragma unroll
        for (int kp = 0; kp < 4; ++kp) {
            uint32_t pa[4];
            pa[0] = pack_h2(sacc[2 * kp][0],     sacc[2 * kp][1]);
            pa[1] = pack_h2(sacc[2 * kp][2],     sacc[2 * kp][3]);
            pa[2] = pack_h2(sacc[2 * kp + 1][0], sacc[2 * kp + 1][1]);
            pa[3] = pack_h2(sacc[2 * kp + 1][2], sacc[2 * kp + 1][3]);
            #pragma unroll
            for (int j = 0; j < 16; ++j) {
                uint32_t vb[2];
                *(uint2*)vb = *(const uint2*)&VF[(j * 4 + kp) * 68 + lane * 2];
                mma_f16(oacc[j], pa, vb);
            }
        }
    }

    // ---- epilogue: normalize, write fp16 attn ----
    float il0 = 1.0f / l0, il1 = 1.0f / l1;
    __half* ob = attn_out + (size_t)(b * SS + qt * 64 + wid * 16) * HH + h * HDIM;
    #pragma unroll
    for (int j = 0; j < 16; ++j) {
        int col = j * 8 + 2 * lt;
        *(__half2*)&ob[(size_t)lg * HH + col] =
            __floats2half2_rn(oacc[j][0] * il0, oacc[j][1] * il0);
        *(__half2*)&ob[(size_t)(lg + 8) * HH + col] =
            __floats2half2_rn(oacc[j][2] * il1, oacc[j][3] * il1);
    }
}

// ---------------------------------------------------------------------------
extern "C" void kernel_launch(void* const* d_in, const int* in_sizes, int n_in,
                              void* d_out, int out_size)
{
    const float* hs      = (const float*)d_in[0];
    const float* w_qkv   = (const float*)d_in[1];
    const float* b_qkv   = (const float*)d_in[2];
    const float* w_dense = (const float*)d_in[3];
    const int*   pos     = (const int*)d_in[4];
    float* out = (float*)d_out;

    __half *qkv_ptr, *attn_ptr, *wt_ptr;
    cudaGetSymbolAddress((void**)&qkv_ptr, g_qkv);
    cudaGetSymbolAddress((void**)&attn_ptr, g_attn);
    cudaGetSymbolAddress((void**)&wt_ptr, g_wt);

    cudaFuncSetAttribute(mma_gemm_f16<true>,
                         cudaFuncAttributeMaxDynamicSharedMemorySize, GM_SMEM_BYTES);
    cudaFuncSetAttribute(mma_gemm_f16<false>,
                         cudaFuncAttributeMaxDynamicSharedMemorySize, GM_SMEM_BYTES);

    // 1) Transpose + fp16 convert w_qkv: [4096,4608] -> [4608,4096] fp16
    transpose_f16_kernel<<<dim3(QKV_N / 32, HH / 32), dim3(32, 8)>>>(w_qkv, wt_ptr, HH, QKV_N);

    // 2) QKV projection + bias (fp16 tensor cores; A fp32 in, C fp16 out)
    mma_gemm_f16<true><<<dim3(QKV_N / 256, TOKENS / 128), 256, GM_SMEM_BYTES>>>(
        hs, wt_ptr, b_qkv, qkv_ptr, TOKENS, QKV_N, HH);

    // 3) RoPE in place (fp16 storage, fp32 math)
    {
        int total = TOKENS * (NHEAD + NKVH) * (ROT / 2);
        rope_kernel<<<(total + 255) / 256, 256>>>(qkv_ptr, pos);
    }

    // 4) Flash attention (fp16 tensor cores, register-resident P)
    flash_mma_kernel<<<dim3(SS / 64, BB * NHEAD), 128>>>(qkv_ptr, attn_ptr);

    // 5) Transpose + fp16 convert w_dense: [4096,4096] -> [4096,4096] fp16
    transpose_f16_kernel<<<dim3(HH / 32, HH / 32), dim3(32, 8)>>>(w_dense, wt_ptr, HH, HH);

    // 6) Dense projection (fp16 tensor cores; A fp16, C fp32 out)
    mma_gemm_f16<false><<<dim3(HH / 256, TOKENS / 128), 256, GM_SMEM_BYTES>>>(
        attn_ptr, wt_ptr, nullptr, out, TOKENS, HH, HH);
}

// round 9
// speedup vs baseline: 8.5488x; 1.1756x over previous
#include <cuda_runtime.h>
#include <cuda_fp16.h>
#include <math.h>
#include <float.h>
#include <cstdint>

// Problem constants
#define BB 2
#define SS 2048
#define HH 4096
#define NHEAD 32
#define NKVH 2
#define HDIM 128
#define ROT 64
#define QKV_N ((NHEAD + 2*NKVH) * HDIM)   // 4608
#define TOKENS (BB*SS)                     // 4096

// Scratch (device globals; allocation-free) — all fp16
__device__ __half g_qkv[(size_t)TOKENS * QKV_N];
__device__ __half g_attn[(size_t)TOKENS * HH];
__device__ __half g_wt[(size_t)QKV_N * HH];
__device__ __half g_vt[(size_t)BB * NKVH * HDIM * SS];   // V transposed: [b][kvh][d][t]

// mma.sync m16n8k16 fp16 -> fp32 accum
__device__ __forceinline__ void mma_f16(float* c, const uint32_t* a, const uint32_t* b) {
    asm volatile("mma.sync.aligned.m16n8k16.row.col.f32.f16.f16.f32 "
        "{%0,%1,%2,%3}, {%4,%5,%6,%7}, {%8,%9}, {%0,%1,%2,%3};"
        : "+f"(c[0]), "+f"(c[1]), "+f"(c[2]), "+f"(c[3])
        : "r"(a[0]), "r"(a[1]), "r"(a[2]), "r"(a[3]), "r"(b[0]), "r"(b[1]));
}

__device__ __forceinline__ uint32_t pack_h2(float x, float y) {
    __half2 h = __floats2half2_rn(x, y);
    return *(uint32_t*)&h;
}

__device__ __forceinline__ uint32_t smem_u32(const void* p) {
    uint32_t a;
    asm("{ .reg .u64 t; cvta.to.shared.u64 t, %1; cvt.u32.u64 %0, t; }" : "=r"(a) : "l"(p));
    return a;
}

#define CP16(dst, src) \
    asm volatile("cp.async.cg.shared.global [%0], [%1], 16;" :: "r"(dst), "l"(src) : "memory")
#define CP_COMMIT() asm volatile("cp.async.commit_group;" ::: "memory")
#define CP_WAIT1()  asm volatile("cp.async.wait_group 1;" ::: "memory")
#define CP_WAIT0()  asm volatile("cp.async.wait_group 0;" ::: "memory")

#define LDSM4(r0, r1, r2, r3, addr) \
    asm volatile("ldmatrix.sync.aligned.m8n8.x4.shared.b16 {%0,%1,%2,%3}, [%4];" \
        : "=r"(r0), "=r"(r1), "=r"(r2), "=r"(r3) : "r"(addr))

// ---------------------------------------------------------------------------
// Weight transpose + fp16 convert: W[K,N] fp32 row-major -> Wt[N,K] fp16
// ---------------------------------------------------------------------------
__global__ __launch_bounds__(256)
void transpose_f16_kernel(const float* __restrict__ W, __half* __restrict__ Wt, int K, int N)
{
    __shared__ float t[32][33];
    const int n0 = blockIdx.x * 32;
    const int k0 = blockIdx.y * 32;
    const int x = threadIdx.x, y = threadIdx.y;   // 32 x 8
    #pragma unroll
    for (int j = 0; j < 32; j += 8)
        t[y + j][x] = W[(size_t)(k0 + y + j) * N + n0 + x];
    __syncthreads();
    const int tid = y * 32 + x;
    #pragma unroll
    for (int p = 0; p < 2; ++p) {
        int task = p * 256 + tid;
        int r = task >> 4;
        int c = task & 15;
        __half2 h = __floats2half2_rn(t[2 * c][r], t[2 * c + 1][r]);
        *(__half2*)&Wt[(size_t)(n0 + r) * K + k0 + 2 * c] = h;
    }
}

// ---------------------------------------------------------------------------
// V transpose: g_qkv V region [token][d] -> g_vt [b][kvh][d][token]
// ---------------------------------------------------------------------------
__global__ __launch_bounds__(256)
void vtrans_kernel(const __half* __restrict__ qkv, __half* __restrict__ vt)
{
    __shared__ __half t[32][34];
    const int bk = blockIdx.z;            // b*NKVH + kvh
    const int d0 = blockIdx.y * 32;
    const int t0 = blockIdx.x * 32;
    const int b = bk >> 1, kvh = bk & 1;
    const int x = threadIdx.x, y = threadIdx.y;   // 32 x 8
    const __half* src = qkv + (size_t)(b * SS + t0) * QKV_N
                        + (NHEAD + NKVH) * HDIM + kvh * HDIM + d0;
    #pragma unroll
    for (int j = 0; j < 32; j += 8)
        t[y + j][x] = src[(size_t)(y + j) * QKV_N + x];   // [tok_local][d_local]
    __syncthreads();
    __half* dst = vt + ((size_t)bk * HDIM + d0) * SS + t0;
    #pragma unroll
    for (int j = 0; j < 32; j += 8)
        dst[(size_t)(y + j) * SS + x] = t[x][y + j];      // [d_local][tok_local]
}

// ---------------------------------------------------------------------------
// fp16 tensor-core GEMM (unchanged from round 8 — at HMMA ceiling)
// ---------------------------------------------------------------------------
#define GM_SMEM_WORDS (2*2112 + 2*4352)
#define GM_SMEM_BYTES (GM_SMEM_WORDS * 4)   // 51712

template<bool QKV>
__global__ __launch_bounds__(256, 1)
void mma_gemm_f16(const void* __restrict__ Av, const __half* __restrict__ Bt,
                  const float* __restrict__ bias, void* __restrict__ Cv,
                  int M, int N, int K)
{
    extern __shared__ uint32_t smw[];
    uint32_t* Asm = smw;
    uint32_t* Bsm = smw + 4224;

    const float*  Af = (const float*)Av;
    const __half* Ah = (const __half*)Av;

    const int tid  = threadIdx.x;
    const int wid  = tid >> 5;
    const int lane = tid & 31;
    const int lg   = lane >> 2;
    const int lt   = lane & 3;
    const int m_warp = (wid & 1) * 64;
    const int n_warp = (wid >> 1) * 64;
    const int rowBase = blockIdx.y * 128;
    const int colBase = blockIdx.x * 256;

    int fr[4], fq[4];
    #pragma unroll
    for (int p = 0; p < 4; ++p) {
        int idx = p * 256 + tid;
        fr[p] = idx >> 3;
        fq[p] = (idx & 7) * 4;
    }
    int br[8], bq[8];
    #pragma unroll
    for (int p = 0; p < 8; ++p) {
        int idx = p * 256 + tid;
        br[p] = idx >> 3;
        bq[p] = (idx & 7) * 4;
    }

    float acc[4][8][4];
    #pragma unroll
    for (int i = 0; i < 4; ++i)
        #pragma unroll
        for (int j = 0; j < 8; ++j)
            #pragma unroll
            for (int r = 0; r < 4; ++r) acc[i][j][r] = 0.f;

    float4 aSf[4]; uint2 aSh[4]; uint2 bS[8];

    auto ldg_tiles = [&](int kt) {
        #pragma unroll
        for (int p = 0; p < 4; ++p) {
            if (QKV) aSf[p] = *(const float4*)&Af[(size_t)(rowBase + fr[p]) * K + kt + fq[p]];
            else     aSh[p] = *(const uint2*)&Ah[(size_t)(rowBase + fr[p]) * K + kt + fq[p]];
        }
        #pragma unroll
        for (int p = 0; p < 8; ++p)
            bS[p] = *(const uint2*)&Bt[(size_t)(colBase + br[p]) * K + kt + bq[p]];
    };
    auto sts_tiles = [&](int buf) {
        #pragma unroll
        for (int p = 0; p < 4; ++p) {
            int r = fr[p], q = fq[p];
            int lt0 = (q & 7) >> 1;
            int kbit = (q >> 3) & 1;
            uint32_t h0, h1;
            if (QKV) { h0 = pack_h2(aSf[p].x, aSf[p].y); h1 = pack_h2(aSf[p].z, aSf[p].w); }
            else     { h0 = aSh[p].x; h1 = aSh[p].y; }
            int wA = ((r >> 4) * 2 + (q >> 4)) * 132
                     + ((r & 7) * 4 + lt0) * 4 + ((r >> 3) & 1) + 2 * kbit;
            Asm[buf * 2112 + wA]     = h0;
            Asm[buf * 2112 + wA + 4] = h1;
        }
        #pragma unroll
        for (int p = 0; p < 8; ++p) {
            int n = br[p], q = bq[p];
            int lt0 = (q & 7) >> 1;
            int kbit = (q >> 3) & 1;
            int wB = ((n >> 3) * 2 + (q >> 4)) * 68
                     + ((n & 7) * 4 + lt0) * 2 + kbit;
            Bsm[buf * 4352 + wB]     = bS[p].x;
            Bsm[buf * 4352 + wB + 2] = bS[p].y;
        }
    };
    auto mma_tile = [&](int buf) {
        const uint32_t* Ab = Asm + buf * 2112 + (wid & 1) * 1056 + lane * 4;
        const uint32_t* Bb = Bsm + buf * 4352 + (wid >> 1) * 1088 + lane * 2;
        #pragma unroll
        for (int ks = 0; ks < 2; ++ks) {
            uint32_t afr[4][4], bfr[8][2];
            #pragma unroll
            for (int i = 0; i < 4; ++i)
                *(uint4*)afr[i] = *(const uint4*)(Ab + (i * 2 + ks) * 132);
            #pragma unroll
            for (int j = 0; j < 8; ++j)
                *(uint2*)bfr[j] = *(const uint2*)(Bb + (j * 2 + ks) * 68);
            #pragma unroll
            for (int i = 0; i < 4; ++i)
                #pragma unroll
                for (int j = 0; j < 8; ++j)
                    mma_f16(acc[i][j], afr[i], bfr[j]);
        }
    };

    const int NIT = K / 32;
    ldg_tiles(0);
    sts_tiles(0);
    __syncthreads();

    for (int t = 0; t < NIT; ++t) {
        if (t + 1 < NIT) ldg_tiles((t + 1) * 32);
        mma_tile(t & 1);
        if (t + 1 < NIT) sts_tiles((t + 1) & 1);
        __syncthreads();
    }

    #pragma unroll
    for (int i = 0; i < 4; ++i) {
        #pragma unroll
        for (int j = 0; j < 8; ++j) {
            int row = rowBase + m_warp + i * 16 + lg;
            int col = colBase + n_warp + j * 8 + lt * 2;
            if (QKV) {
                __half* C = (__half*)Cv;
                float b0 = bias[col], b1 = bias[col + 1];
                *(__half2*)&C[(size_t)row * N + col] =
                    __floats2half2_rn(acc[i][j][0] + b0, acc[i][j][1] + b1);
                *(__half2*)&C[(size_t)(row + 8) * N + col] =
                    __floats2half2_rn(acc[i][j][2] + b0, acc[i][j][3] + b1);
            } else {
                float* C = (float*)Cv;
                float2 v0 = { acc[i][j][0], acc[i][j][1] };
                float2 v1 = { acc[i][j][2], acc[i][j][3] };
                *(float2*)&C[(size_t)row * N + col]       = v0;
                *(float2*)&C[(size_t)(row + 8) * N + col] = v1;
            }
        }
    }
}

// ---------------------------------------------------------------------------
// GLM RoPE, in-place on fp16 qkv (rotation math in fp32)
// ---------------------------------------------------------------------------
__global__ void rope_kernel(__half* __restrict__ qkv, const int* __restrict__ positions)
{
    int idx = blockIdx.x * blockDim.x + threadIdx.x;
    const int total = TOKENS * (NHEAD + NKVH) * (ROT / 2);
    if (idx >= total) return;
    int i    = idx & 31;
    int head = (idx >> 5) % (NHEAD + NKVH);
    int tok  = idx / ((NHEAD + NKVH) * 32);

    float pos = (float)positions[tok];
    float inv = __powf(10000.0f, -(float)i * (1.0f / 32.0f));
    float ang = pos * inv;
    float c, s;
    sincosf(ang, &s, &c);
    int col = (head < NHEAD) ? head * HDIM : (NHEAD * HDIM + (head - NHEAD) * HDIM);
    __half2* p = (__half2*)(qkv + (size_t)tok * QKV_N + col + 2 * i);
    float2 x = __half22float2(*p);
    *p = __floats2half2_rn(x.x * c - x.y * s, x.x * s + x.y * c);
}

// ---------------------------------------------------------------------------
// Flash attention v3: cp.async double-buffered fills + ldmatrix fragments.
// Block: 64 q-rows x 1 head, 128 threads (4 warps x 16 q-rows). KV tile 64.
// SMEM: K buf = 64 rows x 272B (17 uint4, pad 1)  -> 17408B x2
//       V^T buf = 128 rows x 144B (9 uint4, pad 1) -> 18432B x2
// K row-major [n][d]; V^T row-major [d][tok] (from g_vt). B-frags via
// ldmatrix.x4 (lane l of 8x8 b16 tile = row l>>2, half2 col l&3 = mma B-frag).
// ---------------------------------------------------------------------------
#define FL_K_BYTES 17408
#define FL_V_BYTES 18432
#define FL_SMEM_BYTES (2*FL_K_BYTES + 2*FL_V_BYTES)   // 71680

__global__ __launch_bounds__(128, 3)
void flash_mma_kernel(const __half* __restrict__ qkv, const __half* __restrict__ vt,
                      __half* __restrict__ attn_out)
{
    extern __shared__ uint4 smu[];
    const uint32_t sb = smem_u32(smu);

    const int qt = blockIdx.x;               // 0..31
    const int bh = blockIdx.y;               // 0..63
    const int b  = bh >> 5;
    const int h  = bh & 31;
    const int kvh = h >> 4;
    const int tid = threadIdx.x;
    const int wid = tid >> 5;
    const int lane = tid & 31;
    const int lg = lane >> 2, lt = lane & 3;
    const int gq = lane >> 3, rq = lane & 7;  // ldmatrix address groups
    const float scale = 0.08838834764831845f;

    // ---- stage Q (64 rows x 16 uint4) into smem rows of stride 17 ----
    const uint4* qg4 = (const uint4*)(qkv + (size_t)(b * SS + qt * 64) * QKV_N + h * HDIM);
    #pragma unroll
    for (int p = 0; p < 8; ++p) {
        int idx = p * 128 + tid;
        smu[(idx >> 4) * 17 + (idx & 15)] = qg4[(size_t)(idx >> 4) * 576 + (idx & 15)];
    }
    __syncthreads();
    uint32_t qa[8][4];
    {
        const uint32_t* Qw = (const uint32_t*)smu;
        int q0 = (wid * 16 + lg) * 68 + lt;
        int q1 = q0 + 8 * 68;
        #pragma unroll
        for (int kc = 0; kc < 8; ++kc) {
            qa[kc][0] = Qw[q0 + kc * 8];
            qa[kc][1] = Qw[q1 + kc * 8];
            qa[kc][2] = Qw[q0 + kc * 8 + 4];
            qa[kc][3] = Qw[q1 + kc * 8 + 4];
        }
    }
    __syncthreads();

    float oacc[16][4];
    #pragma unroll
    for (int j = 0; j < 16; ++j)
        #pragma unroll
        for (int r = 0; r < 4; ++r) oacc[j][r] = 0.f;
    float m0 = -3.0e38f, m1 = -3.0e38f, l0 = 0.f, l1 = 0.f;

    const __half* kbase = qkv + (size_t)b * SS * QKV_N + NHEAD * HDIM + kvh * HDIM;
    const __half* vbase = vt + (size_t)(b * NKVH + kvh) * HDIM * SS;

    auto fill = [&](int kt, int buf) {
        uint32_t Kd = sb + buf * FL_K_BYTES;
        uint32_t Vd = sb + 2 * FL_K_BYTES + buf * FL_V_BYTES;
        const uint4* ks = (const uint4*)(kbase + (size_t)(kt * 64) * QKV_N);
        #pragma unroll
        for (int p = 0; p < 8; ++p) {
            int idx = p * 128 + tid;
            int n = idx >> 4, c = idx & 15;
            CP16(Kd + (uint32_t)(n * 17 + c) * 16, ks + (size_t)n * 576 + c);
        }
        const uint4* vs = (const uint4*)(vbase + kt * 64);
        #pragma unroll
        for (int p = 0; p < 8; ++p) {
            int idx = p * 128 + tid;
            int f = idx >> 3, c = idx & 7;
            CP16(Vd + (uint32_t)(f * 9 + c) * 16, vs + (size_t)f * 256 + c);
        }
    };

    fill(0, 0);
    CP_COMMIT();

    const int row0g = qt * 64 + wid * 16 + lg;
    const int row1g = row0g + 8;

    for (int kt = 0; kt <= qt; ++kt) {
        if (kt < qt) { fill(kt + 1, (kt + 1) & 1); CP_COMMIT(); CP_WAIT1(); }
        else         { CP_WAIT0(); }
        __syncthreads();

        const uint32_t Kb = sb + (kt & 1) * FL_K_BYTES
                            + rq * 272 + (gq >> 1) * 32 + (gq & 1) * 16;
        const uint32_t Vb = sb + 2 * FL_K_BYTES + (kt & 1) * FL_V_BYTES
                            + rq * 144 + (gq >> 1) * 32 + (gq & 1) * 16;

        // ---- S = Q K^T : 16x64 per warp ----
        float sacc[8][4];
        #pragma unroll
        for (int j = 0; j < 8; ++j)
            #pragma unroll
            for (int r = 0; r < 4; ++r) sacc[j][r] = 0.f;

        #pragma unroll
        for (int kp2 = 0; kp2 < 4; ++kp2) {
            #pragma unroll
            for (int j = 0; j < 8; ++j) {
                uint32_t b0, b1, b2, b3;
                LDSM4(b0, b1, b2, b3, Kb + j * 2176 + kp2 * 64);
                uint32_t be[2] = { b0, b1 }, bo[2] = { b2, b3 };
                mma_f16(sacc[j], qa[2 * kp2],     be);
                mma_f16(sacc[j], qa[2 * kp2 + 1], bo);
            }
        }

        // ---- scale + causal mask ----
        #pragma unroll
        for (int j = 0; j < 8; ++j)
            #pragma unroll
            for (int r = 0; r < 4; ++r) sacc[j][r] *= scale;
        if (kt == qt) {
            #pragma unroll
            for (int j = 0; j < 8; ++j) {
                int col = kt * 64 + j * 8 + 2 * lt;
                if (col     > row0g) sacc[j][0] = -3.0e38f;
                if (col + 1 > row0g) sacc[j][1] = -3.0e38f;
                if (col     > row1g) sacc[j][2] = -3.0e38f;
                if (col + 1 > row1g) sacc[j][3] = -3.0e38f;
            }
        }

        // ---- online softmax (rows lg / lg+8; quad-lane reduce) ----
        float mx0 = -3.0e38f, mx1 = -3.0e38f;
        #pragma unroll
        for (int j = 0; j < 8; ++j) {
            mx0 = fmaxf(mx0, fmaxf(sacc[j][0], sacc[j][1]));
            mx1 = fmaxf(mx1, fmaxf(sacc[j][2], sacc[j][3]));
        }
        mx0 = fmaxf(mx0, __shfl_xor_sync(0xffffffffu, mx0, 1));
        mx0 = fmaxf(mx0, __shfl_xor_sync(0xffffffffu, mx0, 2));
        mx1 = fmaxf(mx1, __shfl_xor_sync(0xffffffffu, mx1, 1));
        mx1 = fmaxf(mx1, __shfl_xor_sync(0xffffffffu, mx1, 2));
        float nm0 = fmaxf(m0, mx0), nm1 = fmaxf(m1, mx1);
        float a0 = __expf(m0 - nm0), a1 = __expf(m1 - nm1);
        m0 = nm0; m1 = nm1;
        float rs0 = 0.f, rs1 = 0.f;
        #pragma unroll
        for (int j = 0; j < 8; ++j) {
            sacc[j][0] = __expf(sacc[j][0] - nm0);
            sacc[j][1] = __expf(sacc[j][1] - nm0);
            sacc[j][2] = __expf(sacc[j][2] - nm1);
            sacc[j][3] = __expf(sacc[j][3] - nm1);
            rs0 += sacc[j][0] + sacc[j][1];
            rs1 += sacc[j][2] + sacc[j][3];
        }
        rs0 += __shfl_xor_sync(0xffffffffu, rs0, 1);
        rs0 += __shfl_xor_sync(0xffffffffu, rs0, 2);
        rs1 += __shfl_xor_sync(0xffffffffu, rs1, 1);
        rs1 += __shfl_xor_sync(0xffffffffu, rs1, 2);
        l0 = l0 * a0 + rs0;
        l1 = l1 * a1 + rs1;

        #pragma unroll
        for (int j = 0; j < 16; ++j) {
            oacc[j][0] *= a0; oacc[j][1] *= a0;
            oacc[j][2] *= a1; oacc[j][3] *= a1;
        }

        // ---- P A-frags from S C-frags (registers only) ----
        uint32_t pa[4][4];
        #pragma unroll
        for (int kp = 0; kp < 4; ++kp) {
            pa[kp][0] = pack_h2(sacc[2 * kp][0],     sacc[2 * kp][1]);
            pa[kp][1] = pack_h2(sacc[2 * kp][2],     sacc[2 * kp][3]);
            pa[kp][2] = pack_h2(sacc[2 * kp + 1][0], sacc[2 * kp + 1][1]);
            pa[kp][3] = pack_h2(sacc[2 * kp + 1][2], sacc[2 * kp + 1][3]);
        }

        // ---- O += P V ----
        #pragma unroll
        for (int kp2 = 0; kp2 < 2; ++kp2) {
            #pragma unroll
            for (int jf = 0; jf < 16; ++jf) {
                uint32_t r0, r1, r2, r3;
                LDSM4(r0, r1, r2, r3, Vb + jf * 1152 + kp2 * 64);
                uint32_t ve[2] = { r0, r1 }, vo[2] = { r2, r3 };
                mma_f16(oacc[jf], pa[2 * kp2],     ve);
                mma_f16(oacc[jf], pa[2 * kp2 + 1], vo);
            }
        }
        __syncthreads();
    }

    // ---- epilogue: normalize, write fp16 attn ----
    float il0 = 1.0f / l0, il1 = 1.0f / l1;
    __half* ob = attn_out + (size_t)(b * SS + qt * 64 + wid * 16) * HH + h * HDIM;
    #pragma unroll
    for (int j = 0; j < 16; ++j) {
        int col = j * 8 + 2 * lt;
        *(__half2*)&ob[(size_t)lg * HH + col] =
            __floats2half2_rn(oacc[j][0] * il0, oacc[j][1] * il0);
        *(__half2*)&ob[(size_t)(lg + 8) * HH + col] =
            __floats2half2_rn(oacc[j][2] * il1, oacc[j][3] * il1);
    }
}

// ---------------------------------------------------------------------------
extern "C" void kernel_launch(void* const* d_in, const int* in_sizes, int n_in,
                              void* d_out, int out_size)
{
    const float* hs      = (const float*)d_in[0];
    const float* w_qkv   = (const float*)d_in[1];
    const float* b_qkv   = (const float*)d_in[2];
    const float* w_dense = (const float*)d_in[3];
    const int*   pos     = (const int*)d_in[4];
    float* out = (float*)d_out;

    __half *qkv_ptr, *attn_ptr, *wt_ptr, *vt_ptr;
    cudaGetSymbolAddress((void**)&qkv_ptr, g_qkv);
    cudaGetSymbolAddress((void**)&attn_ptr, g_attn);
    cudaGetSymbolAddress((void**)&wt_ptr, g_wt);
    cudaGetSymbolAddress((void**)&vt_ptr, g_vt);

    cudaFuncSetAttribute(mma_gemm_f16<true>,
                         cudaFuncAttributeMaxDynamicSharedMemorySize, GM_SMEM_BYTES);
    cudaFuncSetAttribute(mma_gemm_f16<false>,
                         cudaFuncAttributeMaxDynamicSharedMemorySize, GM_SMEM_BYTES);
    cudaFuncSetAttribute(flash_mma_kernel,
                         cudaFuncAttributeMaxDynamicSharedMemorySize, FL_SMEM_BYTES);

    // 1) Transpose + fp16 convert w_qkv
    transpose_f16_kernel<<<dim3(QKV_N / 32, HH / 32), dim3(32, 8)>>>(w_qkv, wt_ptr, HH, QKV_N);

    // 2) QKV projection + bias (fp16 tensor cores)
    mma_gemm_f16<true><<<dim3(QKV_N / 256, TOKENS / 128), 256, GM_SMEM_BYTES>>>(
        hs, wt_ptr, b_qkv, qkv_ptr, TOKENS, QKV_N, HH);

    // 3) RoPE in place (Q and K only)
    {
        int total = TOKENS * (NHEAD + NKVH) * (ROT / 2);
        rope_kernel<<<(total + 255) / 256, 256>>>(qkv_ptr, pos);
    }

    // 4) V transpose (V untouched by RoPE)
    vtrans_kernel<<<dim3(SS / 32, HDIM / 32, BB * NKVH), dim3(32, 8)>>>(qkv_ptr, vt_ptr);

    // 5) Flash attention (cp.async + ldmatrix)
    flash_mma_kernel<<<dim3(SS / 64, BB * NHEAD), 128, FL_SMEM_BYTES>>>(
        qkv_ptr, vt_ptr, attn_ptr);

    // 6) Transpose + fp16 convert w_dense
    transpose_f16_kernel<<<dim3(HH / 32, HH / 32), dim3(32, 8)>>>(w_dense, wt_ptr, HH, HH);

    // 7) Dense projection (fp16 tensor cores)
    mma_gemm_f16<false><<<dim3(HH / 256, TOKENS / 128), 256, GM_SMEM_BYTES>>>(
        attn_ptr, wt_ptr, nullptr, out, TOKENS, HH, HH);
}